// round 9
// baseline (speedup 1.0000x reference)
#include <cuda_runtime.h>
#include <cuda_fp16.h>
#include <cstdint>

// Local Scale Attention — round 6 (= round 5 + alignment fix):
// tf32 mma.sync GEMMs (at HMMA floor) + fp32-accumulate attention with
// fp16 K/V smem storage (8B-aligned, conflict-free strides) and fused
// S+softmax. B=2048, N=84, C=256, H=8, hd=32.

#define BATCH 2048
#define NTOK  84
#define DIM   256
#define HEADS 8

typedef unsigned long long u64;

__device__ float g_qkv [(size_t)BATCH * NTOK * 768];   // 528 MB
__device__ float g_attn[(size_t)BATCH * NTOK * DIM];   // 176 MB
__device__ float g_WT  [768 * 256];
__device__ float g_WpT [256 * 256];
__device__ float g_bias[HEADS * NTOK * NTOK];

// ---------------------------------------------------------------------------
// helpers
// ---------------------------------------------------------------------------
__device__ __forceinline__ u64 ffma2(u64 a, u64 b, u64 c) {
    u64 d;
    asm("fma.rn.f32x2 %0, %1, %2, %3;" : "=l"(d) : "l"(a), "l"(b), "l"(c));
    return d;
}
__device__ __forceinline__ float hsum2(u64 v) {
    float lo, hi;
    asm("mov.b64 {%0, %1}, %2;" : "=f"(lo), "=f"(hi) : "l"(v));
    return lo + hi;
}
__device__ __forceinline__ u64 pack2(float lo, float hi) {
    u64 v;
    asm("mov.b64 %0, {%1, %2};" : "=l"(v) : "f"(lo), "f"(hi));
    return v;
}
__device__ __forceinline__ uint32_t smem_u32(const void* p) {
    uint32_t a;
    asm("{ .reg .u64 t; cvta.to.shared.u64 t, %1; cvt.u32.u64 %0, t; }" : "=r"(a) : "l"(p));
    return a;
}
__device__ __forceinline__ void cp_async16(uint32_t dst, const void* src) {
    asm volatile("cp.async.cg.shared.global [%0], [%1], 16;" :: "r"(dst), "l"(src));
}
__device__ __forceinline__ uint32_t tf32u(float x) {
    uint32_t u;
    asm("cvt.rna.tf32.f32 %0, %1;" : "=r"(u) : "f"(x));
    return u;
}
__device__ __forceinline__ float tf32r(float x) { return __uint_as_float(tf32u(x)); }

__device__ __forceinline__ void mma_tf32(float* d, const uint32_t* a, const uint32_t* b) {
    asm volatile(
        "mma.sync.aligned.m16n8k8.row.col.f32.tf32.tf32.f32 "
        "{%0,%1,%2,%3}, {%4,%5,%6,%7}, {%8,%9}, {%0,%1,%2,%3};"
        : "+f"(d[0]), "+f"(d[1]), "+f"(d[2]), "+f"(d[3])
        : "r"(a[0]), "r"(a[1]), "r"(a[2]), "r"(a[3]), "r"(b[0]), "r"(b[1]));
}

// unpack uint2 of 4 halves into two packed-f32x2 u64s
__device__ __forceinline__ void h4_to_2x2(uint2 h, u64& lo, u64& hi) {
    float2 f01 = __half22float2(*reinterpret_cast<__half2*>(&h.x));
    float2 f23 = __half22float2(*reinterpret_cast<__half2*>(&h.y));
    lo = pack2(f01.x, f01.y);
    hi = pack2(f23.x, f23.y);
}

// ---------------------------------------------------------------------------
// prep kernels
// ---------------------------------------------------------------------------
__global__ void wprep_kernel(const float* __restrict__ Wqkv, const float* __restrict__ Wp)
{
    int n = blockIdx.x, k = threadIdx.x;
    if (n < 768) g_WT[n * 256 + k] = tf32r(Wqkv[k * 768 + n]);
    else         g_WpT[(n - 768) * 256 + k] = tf32r(Wp[k * 256 + (n - 768)]);
}

__global__ void bias_kernel(const float* __restrict__ table, const int* __restrict__ ridx)
{
    int i = blockIdx.x * blockDim.x + threadIdx.x;
    if (i < NTOK * NTOK) {
        int r = ridx[i];
        #pragma unroll
        for (int h = 0; h < HEADS; ++h)
            g_bias[h * (NTOK * NTOK) + i] = table[r * HEADS + h];
    }
}

// ---------------------------------------------------------------------------
// tf32 GEMM via mma.sync (unchanged — at the HMMA-issue floor).
// grid = (ncols/256, Mrows/128). 512 threads = 16 warps as 4(M) x 4(N).
// ---------------------------------------------------------------------------
#define GEMM_SMEM 110592

__global__ __launch_bounds__(512, 1)
void gemm_tf32_kernel(const float* __restrict__ A, const float* __restrict__ BT,
                      const float* __restrict__ bias, float* __restrict__ out, int ncols)
{
    extern __shared__ float sm[];
    const uint32_t sb = smem_u32(sm);
    const int tid = threadIdx.x;
    const int w = tid >> 5, lane = tid & 31;
    const int g = lane >> 2, t = lane & 3;
    const int wm = w >> 2, wn = w & 3;
    const int n0 = blockIdx.x * 256;
    const int m0 = blockIdx.y * 128;

    const float* Ab = A + (size_t)m0 * 256;
    const float* Bb = BT + (size_t)n0 * 256;

    auto load_chunk = [&](int kc, int buf) {
        uint32_t ab = sb + buf * (13824 * 4);
        uint32_t bbuf = ab + 4608 * 4;
        int k0 = kc * 32;
        #pragma unroll
        for (int it = 0; it < 2; ++it) {
            int idx = tid + it * 512;
            int r = idx >> 3, c = idx & 7;
            cp_async16(ab + (r * 36 + c * 4) * 4, Ab + r * 256 + k0 + c * 4);
        }
        #pragma unroll
        for (int it = 0; it < 4; ++it) {
            int idx = tid + it * 512;
            int r = idx >> 3, c = idx & 7;
            cp_async16(bbuf + (r * 36 + c * 4) * 4, Bb + r * 256 + k0 + c * 4);
        }
        asm volatile("cp.async.commit_group;" ::: "memory");
    };

    float d[2][8][4];
    #pragma unroll
    for (int i = 0; i < 2; ++i)
        #pragma unroll
        for (int j = 0; j < 8; ++j)
            #pragma unroll
            for (int c = 0; c < 4; ++c) d[i][j][c] = 0.f;

    load_chunk(0, 0);
    load_chunk(1, 1);

    for (int i = 0; i < 8; ++i) {
        int buf = i & 1;
        if (i < 7) asm volatile("cp.async.wait_group 1;" ::: "memory");
        else       asm volatile("cp.async.wait_group 0;" ::: "memory");
        __syncthreads();

        const float* sAb = sm + buf * 13824;
        const float* sBb = sAb + 4608;
        #pragma unroll
        for (int ks = 0; ks < 4; ++ks) {
            uint32_t a[2][4], bf[8][2];
            #pragma unroll
            for (int ii = 0; ii < 2; ++ii) {
                int row = wm * 32 + ii * 16 + g;
                a[ii][0] = tf32u(sAb[ row      * 36 + ks * 8 + t]);
                a[ii][1] = tf32u(sAb[(row + 8) * 36 + ks * 8 + t]);
                a[ii][2] = tf32u(sAb[ row      * 36 + ks * 8 + t + 4]);
                a[ii][3] = tf32u(sAb[(row + 8) * 36 + ks * 8 + t + 4]);
            }
            #pragma unroll
            for (int j = 0; j < 8; ++j) {
                int n = wn * 64 + j * 8 + g;
                bf[j][0] = __float_as_uint(sBb[n * 36 + ks * 8 + t]);
                bf[j][1] = __float_as_uint(sBb[n * 36 + ks * 8 + t + 4]);
            }
            #pragma unroll
            for (int ii = 0; ii < 2; ++ii)
                #pragma unroll
                for (int j = 0; j < 8; ++j)
                    mma_tf32(d[ii][j], a[ii], bf[j]);
        }
        __syncthreads();
        if (i + 2 < 8) load_chunk(i + 2, buf);
    }

    #pragma unroll
    for (int ii = 0; ii < 2; ++ii) {
        int row = m0 + wm * 32 + ii * 16 + g;
        #pragma unroll
        for (int j = 0; j < 8; ++j) {
            int col = n0 + wn * 64 + j * 8 + 2 * t;
            float b0 = bias[col], b1 = bias[col + 1];
            float2 v0 = make_float2(d[ii][j][0] + b0, d[ii][j][1] + b1);
            float2 v1 = make_float2(d[ii][j][2] + b0, d[ii][j][3] + b1);
            *reinterpret_cast<float2*>(out + (size_t)row * ncols + col) = v0;
            *reinterpret_cast<float2*>(out + (size_t)(row + 8) * ncols + col) = v1;
        }
    }
}

// ---------------------------------------------------------------------------
// attention. grid=2048, 256 threads, 2 CTA/SM.
// smem (bytes):
//   sQ  f32 [88][36]   @ 0       (12672)
//   sS  f32 [84][88]   @ 12672   (29568)   (holds P after softmax)
//   sKh f16 [84] rows, 88 B/row @ 42240 (7392)
//        row stride 88 B = 22 words: 8B-aligned; 22*l mod 32 distinct over
//        each 16-lane phase -> conflict-free uint2 loads.
//   sVt f16 [32] dims,  184 B/row @ 49632 (5888)   V transposed
//        row stride 184 B = 46 words ≡ 14 mod 32: same property.
// total 55520 -> request 55552.
// ---------------------------------------------------------------------------
#define AQ_OFF 0
#define AS_OFF 12672
#define AK_OFF 42240
#define AV_OFF 49632
#define KSTRIDE 88
#define VSTRIDE 184
#define ATTN_SMEM 55552

__global__ __launch_bounds__(256, 2)
void attn_kernel()
{
    extern __shared__ char smc[];
    float* sQ = reinterpret_cast<float*>(smc + AQ_OFF);
    float* sS = reinterpret_cast<float*>(smc + AS_OFF);

    const int tid = threadIdx.x;
    const int w = tid >> 5, l = tid & 31;
    const int b = blockIdx.x;
    const float scale = 0.10910894511799618f;   // 84^-0.5

    const float* qkvb = g_qkv + (size_t)b * (NTOK * 768);

    for (int h = 0; h < HEADS; ++h) {
        __syncthreads();   // protect smem reuse from previous head's PV reads
        // ---- load q (fp32, scaled), k (fp16), v (fp16 transposed) ----
        for (int t = tid; t < 2016; t += 256) {
            int s = t / 672, r = t - s * 672;      // warps never straddle s
            int n = r >> 3, c = r & 7;
            float4 v = *reinterpret_cast<const float4*>(
                qkvb + (size_t)n * 768 + s * 256 + h * 32 + c * 4);
            if (s == 0) {
                v.x *= scale; v.y *= scale; v.z *= scale; v.w *= scale;
                *reinterpret_cast<float4*>(sQ + n * 36 + c * 4) = v;
            } else if (s == 1) {
                uint2 hp;
                __half2 h01 = __floats2half2_rn(v.x, v.y);
                __half2 h23 = __floats2half2_rn(v.z, v.w);
                hp.x = *reinterpret_cast<uint32_t*>(&h01);
                hp.y = *reinterpret_cast<uint32_t*>(&h23);
                *reinterpret_cast<uint2*>(smc + AK_OFF + n * KSTRIDE + c * 8) = hp;
            } else {
                // V^T[dim][token], scalar half stores (2B aligned, always legal)
                *reinterpret_cast<__half*>(smc + AV_OFF + (c * 4 + 0) * VSTRIDE + n * 2) = __float2half_rn(v.x);
                *reinterpret_cast<__half*>(smc + AV_OFF + (c * 4 + 1) * VSTRIDE + n * 2) = __float2half_rn(v.y);
                *reinterpret_cast<__half*>(smc + AV_OFF + (c * 4 + 2) * VSTRIDE + n * 2) = __float2half_rn(v.z);
                *reinterpret_cast<__half*>(smc + AV_OFF + (c * 4 + 3) * VSTRIDE + n * 2) = __float2half_rn(v.w);
            }
        }
        __syncthreads();

        // ---- S = q k^T (+bias), fused softmax, write P to sS ----
        {
            u64 sa[11][3];
            #pragma unroll
            for (int i = 0; i < 11; ++i) { sa[i][0] = 0; sa[i][1] = 0; sa[i][2] = 0; }
            #pragma unroll
            for (int d4 = 0; d4 < 8; ++d4) {
                u64 k0x, k0y, k1x, k1y, k2x = 0, k2y = 0;
                h4_to_2x2(*reinterpret_cast<const uint2*>(smc + AK_OFF +  l       * KSTRIDE + d4 * 8), k0x, k0y);
                h4_to_2x2(*reinterpret_cast<const uint2*>(smc + AK_OFF + (l + 32) * KSTRIDE + d4 * 8), k1x, k1y);
                if (l < 20)
                    h4_to_2x2(*reinterpret_cast<const uint2*>(smc + AK_OFF + (l + 64) * KSTRIDE + d4 * 8), k2x, k2y);
                #pragma unroll
                for (int i = 0; i < 11; ++i) {
                    int row = w + 8 * i;
                    ulonglong2 qv = *reinterpret_cast<const ulonglong2*>(&sQ[row * 36 + d4 * 4]);
                    sa[i][0] = ffma2(qv.x, k0x, sa[i][0]);
                    sa[i][0] = ffma2(qv.y, k0y, sa[i][0]);
                    sa[i][1] = ffma2(qv.x, k1x, sa[i][1]);
                    sa[i][1] = ffma2(qv.y, k1y, sa[i][1]);
                    sa[i][2] = ffma2(qv.x, k2x, sa[i][2]);
                    sa[i][2] = ffma2(qv.y, k2y, sa[i][2]);
                }
            }
            // fused bias + softmax (row owned by this warp) + P store
            const float* gb = g_bias + h * (NTOK * NTOK);
            #pragma unroll
            for (int i = 0; i < 11; ++i) {
                int row = w + 8 * i;
                if (row < NTOK) {                       // warp-uniform
                    float v0 = hsum2(sa[i][0]) + gb[row * 84 + l];
                    float v1 = hsum2(sa[i][1]) + gb[row * 84 + l + 32];
                    float v2 = (l < 20) ? hsum2(sa[i][2]) + gb[row * 84 + l + 64] : -1e30f;
                    float mx = fmaxf(v0, fmaxf(v1, v2));
                    #pragma unroll
                    for (int off = 16; off; off >>= 1)
                        mx = fmaxf(mx, __shfl_xor_sync(0xffffffffu, mx, off));
                    float e0 = __expf(v0 - mx);
                    float e1 = __expf(v1 - mx);
                    float e2 = (l < 20) ? __expf(v2 - mx) : 0.f;
                    float s = e0 + e1 + e2;
                    #pragma unroll
                    for (int off = 16; off; off >>= 1)
                        s += __shfl_xor_sync(0xffffffffu, s, off);
                    float inv = 1.0f / s;
                    sS[row * 88 + l]      = e0 * inv;
                    sS[row * 88 + l + 32] = e1 * inv;
                    if (l < 20) sS[row * 88 + l + 64] = e2 * inv;
                }
            }
        }
        __syncthreads();

        // ---- out = P @ V  (V^T fp16: one LDS.64 per 4 keys per lane) ----
        {
            u64 acc2[11];
            #pragma unroll
            for (int i = 0; i < 11; ++i) acc2[i] = 0;
            #pragma unroll 3
            for (int kq = 0; kq < 21; ++kq) {
                u64 vA, vB;
                h4_to_2x2(*reinterpret_cast<const uint2*>(smc + AV_OFF + l * VSTRIDE + kq * 8), vA, vB);
                #pragma unroll
                for (int i = 0; i < 11; ++i) {
                    int row = w + 8 * i;
                    ulonglong2 p = *reinterpret_cast<const ulonglong2*>(&sS[row * 88 + kq * 4]);
                    acc2[i] = ffma2(p.x, vA, acc2[i]);
                    acc2[i] = ffma2(p.y, vB, acc2[i]);
                }
            }
            float* ga = g_attn + (size_t)b * (NTOK * DIM) + h * 32 + l;
            #pragma unroll
            for (int i = 0; i < 11; ++i) {
                int row = w + 8 * i;
                if (row < NTOK) ga[row * 256] = hsum2(acc2[i]);
            }
        }
    }
}

// ---------------------------------------------------------------------------
extern "C" void kernel_launch(void* const* d_in, const int* in_sizes, int n_in,
                              void* d_out, int out_size)
{
    const float* x     = (const float*)d_in[0];
    const float* Wqkv  = (const float*)d_in[1];
    const float* bqkv  = (const float*)d_in[2];
    const float* Wp    = (const float*)d_in[3];
    const float* bp    = (const float*)d_in[4];
    const float* table = (const float*)d_in[5];
    const int*   ridx  = (const int*)d_in[6];
    float* out = (float*)d_out;

    cudaFuncSetAttribute(gemm_tf32_kernel, cudaFuncAttributeMaxDynamicSharedMemorySize, GEMM_SMEM);
    cudaFuncSetAttribute(attn_kernel, cudaFuncAttributeMaxDynamicSharedMemorySize, ATTN_SMEM);

    float* qkv_sc;  cudaGetSymbolAddress((void**)&qkv_sc, g_qkv);
    float* attn_sc; cudaGetSymbolAddress((void**)&attn_sc, g_attn);
    float* wt_sc;   cudaGetSymbolAddress((void**)&wt_sc, g_WT);
    float* wpt_sc;  cudaGetSymbolAddress((void**)&wpt_sc, g_WpT);

    wprep_kernel<<<1024, 256>>>(Wqkv, Wp);
    bias_kernel<<<28, 256>>>(table, ridx);
    gemm_tf32_kernel<<<dim3(3, 1344), 512, GEMM_SMEM>>>(x, wt_sc, bqkv, qkv_sc, 768);
    attn_kernel<<<BATCH, 256, ATTN_SMEM>>>();
    gemm_tf32_kernel<<<dim3(1, 1344), 512, GEMM_SMEM>>>(attn_sc, wpt_sc, bp, out, 256);
}

// round 10
// speedup vs baseline: 1.0901x; 1.0901x over previous
#include <cuda_runtime.h>
#include <cstdint>

// Local Scale Attention — round 7: tf32 mma.sync for GEMMs AND attention
// (S = QK^T and PV both on tensor cores). B=2048, N=84, C=256, H=8, hd=32.

#define BATCH 2048
#define NTOK  84
#define DIM   256
#define HEADS 8

typedef unsigned long long u64;

__device__ float g_qkv [(size_t)BATCH * NTOK * 768];   // 528 MB
__device__ float g_attn[(size_t)BATCH * NTOK * DIM];   // 176 MB
__device__ float g_WT  [768 * 256];
__device__ float g_WpT [256 * 256];
__device__ float g_bias[HEADS * NTOK * NTOK];

// ---------------------------------------------------------------------------
// helpers
// ---------------------------------------------------------------------------
__device__ __forceinline__ uint32_t smem_u32(const void* p) {
    uint32_t a;
    asm("{ .reg .u64 t; cvta.to.shared.u64 t, %1; cvt.u32.u64 %0, t; }" : "=r"(a) : "l"(p));
    return a;
}
__device__ __forceinline__ void cp_async16(uint32_t dst, const void* src) {
    asm volatile("cp.async.cg.shared.global [%0], [%1], 16;" :: "r"(dst), "l"(src));
}
__device__ __forceinline__ uint32_t tf32u(float x) {
    uint32_t u;
    asm("cvt.rna.tf32.f32 %0, %1;" : "=r"(u) : "f"(x));
    return u;
}
__device__ __forceinline__ float tf32r(float x) { return __uint_as_float(tf32u(x)); }

__device__ __forceinline__ void mma_tf32(float* d, const uint32_t* a, const uint32_t* b) {
    asm volatile(
        "mma.sync.aligned.m16n8k8.row.col.f32.tf32.tf32.f32 "
        "{%0,%1,%2,%3}, {%4,%5,%6,%7}, {%8,%9}, {%0,%1,%2,%3};"
        : "+f"(d[0]), "+f"(d[1]), "+f"(d[2]), "+f"(d[3])
        : "r"(a[0]), "r"(a[1]), "r"(a[2]), "r"(a[3]), "r"(b[0]), "r"(b[1]));
}

// ---------------------------------------------------------------------------
// prep kernels
// ---------------------------------------------------------------------------
__global__ void wprep_kernel(const float* __restrict__ Wqkv, const float* __restrict__ Wp)
{
    int n = blockIdx.x, k = threadIdx.x;
    if (n < 768) g_WT[n * 256 + k] = tf32r(Wqkv[k * 768 + n]);
    else         g_WpT[(n - 768) * 256 + k] = tf32r(Wp[k * 256 + (n - 768)]);
}

__global__ void bias_kernel(const float* __restrict__ table, const int* __restrict__ ridx)
{
    int i = blockIdx.x * blockDim.x + threadIdx.x;
    if (i < NTOK * NTOK) {
        int r = ridx[i];
        #pragma unroll
        for (int h = 0; h < HEADS; ++h)
            g_bias[h * (NTOK * NTOK) + i] = table[r * HEADS + h];
    }
}

// ---------------------------------------------------------------------------
// tf32 GEMM via mma.sync (unchanged — at the HMMA-issue floor).
// grid = (ncols/256, Mrows/128). 512 threads = 16 warps as 4(M) x 4(N).
// ---------------------------------------------------------------------------
#define GEMM_SMEM 110592

__global__ __launch_bounds__(512, 1)
void gemm_tf32_kernel(const float* __restrict__ A, const float* __restrict__ BT,
                      const float* __restrict__ bias, float* __restrict__ out, int ncols)
{
    extern __shared__ float sm[];
    const uint32_t sb = smem_u32(sm);
    const int tid = threadIdx.x;
    const int w = tid >> 5, lane = tid & 31;
    const int g = lane >> 2, t = lane & 3;
    const int wm = w >> 2, wn = w & 3;
    const int n0 = blockIdx.x * 256;
    const int m0 = blockIdx.y * 128;

    const float* Ab = A + (size_t)m0 * 256;
    const float* Bb = BT + (size_t)n0 * 256;

    auto load_chunk = [&](int kc, int buf) {
        uint32_t ab = sb + buf * (13824 * 4);
        uint32_t bbuf = ab + 4608 * 4;
        int k0 = kc * 32;
        #pragma unroll
        for (int it = 0; it < 2; ++it) {
            int idx = tid + it * 512;
            int r = idx >> 3, c = idx & 7;
            cp_async16(ab + (r * 36 + c * 4) * 4, Ab + r * 256 + k0 + c * 4);
        }
        #pragma unroll
        for (int it = 0; it < 4; ++it) {
            int idx = tid + it * 512;
            int r = idx >> 3, c = idx & 7;
            cp_async16(bbuf + (r * 36 + c * 4) * 4, Bb + r * 256 + k0 + c * 4);
        }
        asm volatile("cp.async.commit_group;" ::: "memory");
    };

    float d[2][8][4];
    #pragma unroll
    for (int i = 0; i < 2; ++i)
        #pragma unroll
        for (int j = 0; j < 8; ++j)
            #pragma unroll
            for (int c = 0; c < 4; ++c) d[i][j][c] = 0.f;

    load_chunk(0, 0);
    load_chunk(1, 1);

    for (int i = 0; i < 8; ++i) {
        int buf = i & 1;
        if (i < 7) asm volatile("cp.async.wait_group 1;" ::: "memory");
        else       asm volatile("cp.async.wait_group 0;" ::: "memory");
        __syncthreads();

        const float* sAb = sm + buf * 13824;
        const float* sBb = sAb + 4608;
        #pragma unroll
        for (int ks = 0; ks < 4; ++ks) {
            uint32_t a[2][4], bf[8][2];
            #pragma unroll
            for (int ii = 0; ii < 2; ++ii) {
                int row = wm * 32 + ii * 16 + g;
                a[ii][0] = tf32u(sAb[ row      * 36 + ks * 8 + t]);
                a[ii][1] = tf32u(sAb[(row + 8) * 36 + ks * 8 + t]);
                a[ii][2] = tf32u(sAb[ row      * 36 + ks * 8 + t + 4]);
                a[ii][3] = tf32u(sAb[(row + 8) * 36 + ks * 8 + t + 4]);
            }
            #pragma unroll
            for (int j = 0; j < 8; ++j) {
                int n = wn * 64 + j * 8 + g;
                bf[j][0] = __float_as_uint(sBb[n * 36 + ks * 8 + t]);
                bf[j][1] = __float_as_uint(sBb[n * 36 + ks * 8 + t + 4]);
            }
            #pragma unroll
            for (int ii = 0; ii < 2; ++ii)
                #pragma unroll
                for (int j = 0; j < 8; ++j)
                    mma_tf32(d[ii][j], a[ii], bf[j]);
        }
        __syncthreads();
        if (i + 2 < 8) load_chunk(i + 2, buf);
    }

    #pragma unroll
    for (int ii = 0; ii < 2; ++ii) {
        int row = m0 + wm * 32 + ii * 16 + g;
        #pragma unroll
        for (int j = 0; j < 8; ++j) {
            int col = n0 + wn * 64 + j * 8 + 2 * t;
            float b0 = bias[col], b1 = bias[col + 1];
            float2 v0 = make_float2(d[ii][j][0] + b0, d[ii][j][1] + b1);
            float2 v1 = make_float2(d[ii][j][2] + b0, d[ii][j][3] + b1);
            *reinterpret_cast<float2*>(out + (size_t)row * ncols + col) = v0;
            *reinterpret_cast<float2*>(out + (size_t)(row + 8) * ncols + col) = v1;
        }
    }
}

// ---------------------------------------------------------------------------
// attention via mma.sync tf32. grid=2048, 256 threads (8 warps), 2 CTA/SM.
// smem (floats):
//   sQ  [96][36]  @ 0      tf32-rounded, q pre-scaled; rows 84..95 zero
//   sK  [96][36]  @ 3456   tf32-rounded; rows 84..95 zero
//   sVt [32][100] @ 6912   V^T tf32-rounded; cols 84..99 zero
//   sS  [96][100] @ 10112  raw S, then P (tf32-rounded)
// total 19712 floats = 78848 B.
// All fragment LDS hit bank (4g+t) mod 32 -> conflict-free.
// ---------------------------------------------------------------------------
#define OQ 0
#define OK_ 3456
#define OV 6912
#define OS 10112
#define ATTN_SMEM 78848

__global__ __launch_bounds__(256, 2)
void attn_kernel()
{
    extern __shared__ float smf[];
    float* sQ = smf + OQ;
    float* sK = smf + OK_;
    float* sVt = smf + OV;
    float* sS = smf + OS;

    const int tid = threadIdx.x;
    const int w = tid >> 5, l = tid & 31;
    const int g = l >> 2, t = l & 3;
    const int wm = w >> 2, wn = w & 3;       // 2(M) x 4(N)
    const int b = blockIdx.x;
    const float scale = 0.10910894511799618f;   // 84^-0.5

    // ---- one-time zeroing of pad regions ----
    for (int i = tid; i < 12 * 36; i += 256) { sQ[84 * 36 + i] = 0.f; sK[84 * 36 + i] = 0.f; }
    for (int i = tid; i < 32 * 16; i += 256) sVt[(i >> 4) * 100 + 84 + (i & 15)] = 0.f;

    const float* qkvb = g_qkv + (size_t)b * (NTOK * 768);

    for (int h = 0; h < HEADS; ++h) {
        __syncthreads();   // prev head's PV reads done; pad zeroing done (h=0)
        // ---- load q (scaled,tf32), k (tf32), v^T (tf32) ----
        for (int it = tid; it < 2016; it += 256) {
            int s = it / 672, r = it - s * 672;
            int n = r >> 3, c = r & 7;
            float4 v = *reinterpret_cast<const float4*>(
                qkvb + (size_t)n * 768 + s * 256 + h * 32 + c * 4);
            if (s == 0) {
                v.x = tf32r(v.x * scale); v.y = tf32r(v.y * scale);
                v.z = tf32r(v.z * scale); v.w = tf32r(v.w * scale);
                *reinterpret_cast<float4*>(sQ + n * 36 + c * 4) = v;
            } else if (s == 1) {
                v.x = tf32r(v.x); v.y = tf32r(v.y);
                v.z = tf32r(v.z); v.w = tf32r(v.w);
                *reinterpret_cast<float4*>(sK + n * 36 + c * 4) = v;
            } else {
                sVt[(c * 4 + 0) * 100 + n] = tf32r(v.x);
                sVt[(c * 4 + 1) * 100 + n] = tf32r(v.y);
                sVt[(c * 4 + 2) * 100 + n] = tf32r(v.z);
                sVt[(c * 4 + 3) * 100 + n] = tf32r(v.w);
            }
        }
        __syncthreads();

        // ---- S = Q K^T via mma: warp tile 48(M) x 24(N), k=32 ----
        {
            float c[3][3][4];
            #pragma unroll
            for (int mi = 0; mi < 3; ++mi)
                #pragma unroll
                for (int ni = 0; ni < 3; ++ni)
                    #pragma unroll
                    for (int q = 0; q < 4; ++q) c[mi][ni][q] = 0.f;

            #pragma unroll
            for (int ks = 0; ks < 4; ++ks) {
                uint32_t a[3][4], bf[3][2];
                #pragma unroll
                for (int mi = 0; mi < 3; ++mi) {
                    int row = wm * 48 + mi * 16 + g;
                    a[mi][0] = __float_as_uint(sQ[ row      * 36 + ks * 8 + t]);
                    a[mi][1] = __float_as_uint(sQ[(row + 8) * 36 + ks * 8 + t]);
                    a[mi][2] = __float_as_uint(sQ[ row      * 36 + ks * 8 + t + 4]);
                    a[mi][3] = __float_as_uint(sQ[(row + 8) * 36 + ks * 8 + t + 4]);
                }
                #pragma unroll
                for (int ni = 0; ni < 3; ++ni) {
                    int n = wn * 24 + ni * 8 + g;
                    bf[ni][0] = __float_as_uint(sK[n * 36 + ks * 8 + t]);
                    bf[ni][1] = __float_as_uint(sK[n * 36 + ks * 8 + t + 4]);
                }
                #pragma unroll
                for (int mi = 0; mi < 3; ++mi)
                    #pragma unroll
                    for (int ni = 0; ni < 3; ++ni)
                        mma_tf32(c[mi][ni], a[mi], bf[ni]);
            }
            // write raw S fragments
            #pragma unroll
            for (int mi = 0; mi < 3; ++mi) {
                int row = wm * 48 + mi * 16 + g;
                #pragma unroll
                for (int ni = 0; ni < 3; ++ni) {
                    int col = wn * 24 + ni * 8 + 2 * t;
                    *reinterpret_cast<float2*>(&sS[ row      * 100 + col]) =
                        make_float2(c[mi][ni][0], c[mi][ni][1]);
                    *reinterpret_cast<float2*>(&sS[(row + 8) * 100 + col]) =
                        make_float2(c[mi][ni][2], c[mi][ni][3]);
                }
            }
        }
        __syncthreads();

        // ---- softmax (warp per row) + bias; write P tf32-rounded ----
        {
            const float* gb = g_bias + h * (NTOK * NTOK);
            #pragma unroll
            for (int i = 0; i < 11; ++i) {
                int row = w + 8 * i;
                if (row < NTOK) {                       // warp-uniform
                    float v0 = sS[row * 100 + l]      + gb[row * 84 + l];
                    float v1 = sS[row * 100 + l + 32] + gb[row * 84 + l + 32];
                    float v2 = (l < 20) ? sS[row * 100 + l + 64] + gb[row * 84 + l + 64]
                                        : -1e30f;
                    float mx = fmaxf(v0, fmaxf(v1, v2));
                    #pragma unroll
                    for (int off = 16; off; off >>= 1)
                        mx = fmaxf(mx, __shfl_xor_sync(0xffffffffu, mx, off));
                    float e0 = __expf(v0 - mx);
                    float e1 = __expf(v1 - mx);
                    float e2 = (l < 20) ? __expf(v2 - mx) : 0.f;
                    float s = e0 + e1 + e2;
                    #pragma unroll
                    for (int off = 16; off; off >>= 1)
                        s += __shfl_xor_sync(0xffffffffu, s, off);
                    float inv = 1.0f / s;
                    sS[row * 100 + l]      = tf32r(e0 * inv);
                    sS[row * 100 + l + 32] = tf32r(e1 * inv);
                    if (l < 20) sS[row * 100 + l + 64] = tf32r(e2 * inv);
                }
            }
        }
        __syncthreads();

        // ---- out = P V via mma: warp tile 48(M) x 8(N dims), k=96 ----
        {
            float c2[3][4];
            #pragma unroll
            for (int mi = 0; mi < 3; ++mi)
                #pragma unroll
                for (int q = 0; q < 4; ++q) c2[mi][q] = 0.f;

            #pragma unroll
            for (int ks = 0; ks < 12; ++ks) {
                uint32_t a[3][4], bf[2];
                #pragma unroll
                for (int mi = 0; mi < 3; ++mi) {
                    int row = wm * 48 + mi * 16 + g;
                    a[mi][0] = __float_as_uint(sS[ row      * 100 + ks * 8 + t]);
                    a[mi][1] = __float_as_uint(sS[(row + 8) * 100 + ks * 8 + t]);
                    a[mi][2] = __float_as_uint(sS[ row      * 100 + ks * 8 + t + 4]);
                    a[mi][3] = __float_as_uint(sS[(row + 8) * 100 + ks * 8 + t + 4]);
                }
                int n = wn * 8 + g;
                bf[0] = __float_as_uint(sVt[n * 100 + ks * 8 + t]);
                bf[1] = __float_as_uint(sVt[n * 100 + ks * 8 + t + 4]);
                #pragma unroll
                for (int mi = 0; mi < 3; ++mi)
                    mma_tf32(c2[mi], a[mi], bf);
            }
            float* ga = g_attn + (size_t)b * (NTOK * DIM) + h * 32 + wn * 8 + 2 * t;
            #pragma unroll
            for (int mi = 0; mi < 3; ++mi) {
                int row = wm * 48 + mi * 16 + g;
                if (row < NTOK)
                    *reinterpret_cast<float2*>(ga + row * 256) =
                        make_float2(c2[mi][0], c2[mi][1]);
                if (row + 8 < NTOK)
                    *reinterpret_cast<float2*>(ga + (row + 8) * 256) =
                        make_float2(c2[mi][2], c2[mi][3]);
            }
        }
    }
}

// ---------------------------------------------------------------------------
extern "C" void kernel_launch(void* const* d_in, const int* in_sizes, int n_in,
                              void* d_out, int out_size)
{
    const float* x     = (const float*)d_in[0];
    const float* Wqkv  = (const float*)d_in[1];
    const float* bqkv  = (const float*)d_in[2];
    const float* Wp    = (const float*)d_in[3];
    const float* bp    = (const float*)d_in[4];
    const float* table = (const float*)d_in[5];
    const int*   ridx  = (const int*)d_in[6];
    float* out = (float*)d_out;

    cudaFuncSetAttribute(gemm_tf32_kernel, cudaFuncAttributeMaxDynamicSharedMemorySize, GEMM_SMEM);
    cudaFuncSetAttribute(attn_kernel, cudaFuncAttributeMaxDynamicSharedMemorySize, ATTN_SMEM);

    float* qkv_sc;  cudaGetSymbolAddress((void**)&qkv_sc, g_qkv);
    float* attn_sc; cudaGetSymbolAddress((void**)&attn_sc, g_attn);
    float* wt_sc;   cudaGetSymbolAddress((void**)&wt_sc, g_WT);
    float* wpt_sc;  cudaGetSymbolAddress((void**)&wpt_sc, g_WpT);

    wprep_kernel<<<1024, 256>>>(Wqkv, Wp);
    bias_kernel<<<28, 256>>>(table, ridx);
    gemm_tf32_kernel<<<dim3(3, 1344), 512, GEMM_SMEM>>>(x, wt_sc, bqkv, qkv_sc, 768);
    attn_kernel<<<BATCH, 256, ATTN_SMEM>>>();
    gemm_tf32_kernel<<<dim3(1, 1344), 512, GEMM_SMEM>>>(attn_sc, wpt_sc, bp, out, 256);
}

// round 12
// speedup vs baseline: 2.2258x; 2.0417x over previous
#include <cuda_runtime.h>
#include <cuda_fp16.h>
#include <cstdint>

// Local Scale Attention — round 9: all-fp16 mma.sync (m16n8k16, fp32 accum).
// Identical to round 8 except the xprep launch-grid fix (672 -> 43008 blocks).
// B=2048, N=84, C=256, H=8, hd=32.

#define BATCH 2048
#define NTOK  84
#define DIM   256
#define HEADS 8
#define MROWS (BATCH * NTOK)            // 172032

__device__ __half g_xh   [(size_t)MROWS * 256];   //  88 MB
__device__ __half g_qkvh [(size_t)MROWS * 768];   // 264 MB
__device__ __half g_attnh[(size_t)MROWS * 256];   //  88 MB
__device__ __half g_WTh  [768 * 256];
__device__ __half g_WpTh [256 * 256];
__device__ float  g_bq   [768];
__device__ float  g_bias [HEADS * NTOK * NTOK];

// ---------------------------------------------------------------------------
__device__ __forceinline__ uint32_t smem_u32(const void* p) {
    uint32_t a;
    asm("{ .reg .u64 t; cvta.to.shared.u64 t, %1; cvt.u32.u64 %0, t; }" : "=r"(a) : "l"(p));
    return a;
}
__device__ __forceinline__ void cp_async16(uint32_t dst, const void* src) {
    asm volatile("cp.async.cg.shared.global [%0], [%1], 16;" :: "r"(dst), "l"(src));
}
__device__ __forceinline__ void mma_f16(float* d, const uint32_t* a, const uint32_t* b) {
    asm volatile(
        "mma.sync.aligned.m16n8k16.row.col.f32.f16.f16.f32 "
        "{%0,%1,%2,%3}, {%4,%5,%6,%7}, {%8,%9}, {%0,%1,%2,%3};"
        : "+f"(d[0]), "+f"(d[1]), "+f"(d[2]), "+f"(d[3])
        : "r"(a[0]), "r"(a[1]), "r"(a[2]), "r"(a[3]), "r"(b[0]), "r"(b[1]));
}
__device__ __forceinline__ uint32_t packh2(float a, float b) {
    __half2 h = __floats2half2_rn(a, b);
    return *reinterpret_cast<uint32_t*>(&h);
}

// ---------------------------------------------------------------------------
// prep kernels
// ---------------------------------------------------------------------------
__global__ void xprep_kernel(const float* __restrict__ x)
{
    size_t i = (size_t)blockIdx.x * 256 + threadIdx.x;   // float4 index
    float4 v = reinterpret_cast<const float4*>(x)[i];
    uint2 u;
    u.x = packh2(v.x, v.y);
    u.y = packh2(v.z, v.w);
    reinterpret_cast<uint2*>(g_xh)[i] = u;
}

__global__ void wprep_kernel(const float* __restrict__ Wqkv, const float* __restrict__ Wp,
                             const float* __restrict__ bqkv)
{
    int n = blockIdx.x, k = threadIdx.x;
    const float s = 0.10910894511799618f;   // 84^-0.5 folded into Q projection
    if (n < 768) {
        float f = (n < 256) ? s : 1.f;
        g_WTh[n * 256 + k] = __float2half_rn(Wqkv[k * 768 + n] * f);
        if (k == 0) g_bq[n] = bqkv[n] * f;
    } else {
        g_WpTh[(n - 768) * 256 + k] = __float2half_rn(Wp[k * 256 + (n - 768)]);
    }
}

__global__ void bias_kernel(const float* __restrict__ table, const int* __restrict__ ridx)
{
    int i = blockIdx.x * blockDim.x + threadIdx.x;
    if (i < NTOK * NTOK) {
        int r = ridx[i];
        #pragma unroll
        for (int h = 0; h < HEADS; ++h)
            g_bias[h * (NTOK * NTOK) + i] = table[r * HEADS + h];
    }
}

// ---------------------------------------------------------------------------
// fp16 GEMM: OUT[m][n] = A[m][:256] . BT[n][:256] + bias[n]
// grid (ncols/256, Mrows/128), 512 thr = 16 warps 4(M)x4(N), warp 32x64.
// K in 4 chunks of 64, cp.async double-buffered.
// smem halves: buf stride 27648: A [128][72] @0, B [256][72] @9216. 110592 B.
// ---------------------------------------------------------------------------
#define GEMM_SMEM 110592

template<bool OUT_FP16>
__global__ __launch_bounds__(512, 1)
void gemm_f16_kernel(const __half* __restrict__ A, const __half* __restrict__ BT,
                     const float* __restrict__ bias, void* __restrict__ outp, int ncols)
{
    extern __shared__ __half smh[];
    const uint32_t sb = smem_u32(smh);
    const int tid = threadIdx.x;
    const int w = tid >> 5, lane = tid & 31;
    const int g = lane >> 2, t = lane & 3;
    const int wm = w >> 2, wn = w & 3;
    const int n0 = blockIdx.x * 256;
    const int m0 = blockIdx.y * 128;

    const __half* Ab = A + (size_t)m0 * 256;
    const __half* Bb = BT + (size_t)n0 * 256;

    auto load_chunk = [&](int kc, int buf) {
        uint32_t ab = sb + buf * (27648 * 2);
        uint32_t bb = ab + 9216 * 2;
        int k0 = kc * 64;
        #pragma unroll
        for (int it = 0; it < 2; ++it) {              // A: 1024 x 16B
            int idx = tid + it * 512;
            int r = idx >> 3, c = idx & 7;
            cp_async16(ab + (r * 72 + c * 8) * 2, Ab + (size_t)r * 256 + k0 + c * 8);
        }
        #pragma unroll
        for (int it = 0; it < 4; ++it) {              // B: 2048 x 16B
            int idx = tid + it * 512;
            int r = idx >> 3, c = idx & 7;
            cp_async16(bb + (r * 72 + c * 8) * 2, Bb + (size_t)r * 256 + k0 + c * 8);
        }
        asm volatile("cp.async.commit_group;" ::: "memory");
    };

    float d[2][8][4];
    #pragma unroll
    for (int i = 0; i < 2; ++i)
        #pragma unroll
        for (int j = 0; j < 8; ++j)
            #pragma unroll
            for (int q = 0; q < 4; ++q) d[i][j][q] = 0.f;

    load_chunk(0, 0);
    load_chunk(1, 1);

    for (int i = 0; i < 4; ++i) {
        int buf = i & 1;
        if (i < 3) asm volatile("cp.async.wait_group 1;" ::: "memory");
        else       asm volatile("cp.async.wait_group 0;" ::: "memory");
        __syncthreads();

        const uint32_t* sA = reinterpret_cast<const uint32_t*>(smh + buf * 27648);
        const uint32_t* sB = reinterpret_cast<const uint32_t*>(smh + buf * 27648 + 9216);
        #pragma unroll
        for (int ks = 0; ks < 4; ++ks) {              // 4 x k16 = 64
            uint32_t a[2][4], bf[8][2];
            #pragma unroll
            for (int ii = 0; ii < 2; ++ii) {
                int row = wm * 32 + ii * 16 + g;
                a[ii][0] = sA[ row      * 36 + ks * 8 + t];
                a[ii][1] = sA[(row + 8) * 36 + ks * 8 + t];
                a[ii][2] = sA[ row      * 36 + ks * 8 + t + 4];
                a[ii][3] = sA[(row + 8) * 36 + ks * 8 + t + 4];
            }
            #pragma unroll
            for (int j = 0; j < 8; ++j) {
                int n = wn * 64 + j * 8 + g;
                bf[j][0] = sB[n * 36 + ks * 8 + t];
                bf[j][1] = sB[n * 36 + ks * 8 + t + 4];
            }
            #pragma unroll
            for (int ii = 0; ii < 2; ++ii)
                #pragma unroll
                for (int j = 0; j < 8; ++j)
                    mma_f16(d[ii][j], a[ii], bf[j]);
        }
        __syncthreads();
        if (i + 2 < 4) load_chunk(i + 2, buf);
    }

    #pragma unroll
    for (int ii = 0; ii < 2; ++ii) {
        int row = m0 + wm * 32 + ii * 16 + g;
        #pragma unroll
        for (int j = 0; j < 8; ++j) {
            int col = n0 + wn * 64 + j * 8 + 2 * t;
            float b0 = bias[col], b1 = bias[col + 1];
            if (OUT_FP16) {
                __half* oh = reinterpret_cast<__half*>(outp);
                uint32_t v0 = packh2(d[ii][j][0] + b0, d[ii][j][1] + b1);
                uint32_t v1 = packh2(d[ii][j][2] + b0, d[ii][j][3] + b1);
                *reinterpret_cast<uint32_t*>(oh + (size_t)row * ncols + col) = v0;
                *reinterpret_cast<uint32_t*>(oh + (size_t)(row + 8) * ncols + col) = v1;
            } else {
                float* of = reinterpret_cast<float*>(outp);
                *reinterpret_cast<float2*>(of + (size_t)row * ncols + col) =
                    make_float2(d[ii][j][0] + b0, d[ii][j][1] + b1);
                *reinterpret_cast<float2*>(of + (size_t)(row + 8) * ncols + col) =
                    make_float2(d[ii][j][2] + b0, d[ii][j][3] + b1);
            }
        }
    }
}

// ---------------------------------------------------------------------------
// attention: grid=2048, 192 threads (6 warps), each warp owns 16 q-rows.
// Register softmax, P stays in registers, 2 barriers/head. 4 CTA/SM.
// smem halves: sQ[96][40] @0, sK[96][40] @3840, sVt[32][104] @7680 = 22016 B.
// ---------------------------------------------------------------------------
#define ATTN_SMEM 22016

__global__ __launch_bounds__(192, 4)
void attn_kernel()
{
    extern __shared__ __half smh[];
    __half* sQ = smh;
    __half* sK = smh + 3840;
    unsigned short* sVt = reinterpret_cast<unsigned short*>(smh + 7680);
    const uint32_t* sQw = reinterpret_cast<const uint32_t*>(sQ);
    const uint32_t* sKw = reinterpret_cast<const uint32_t*>(sK);
    const uint32_t* sVw = reinterpret_cast<const uint32_t*>(sVt);

    const int tid = threadIdx.x;
    const int w = tid >> 5, l = tid & 31;
    const int g = l >> 2, t = l & 3;
    const int b = blockIdx.x;

    // zero pad regions once (rows 84..95 of Q,K; cols 84..103 of Vt)
    for (int i = tid; i < 480; i += 192) { sQ[3360 + i] = __ushort_as_half(0); sK[3360 + i] = __ushort_as_half(0); }
    for (int i = tid; i < 32 * 20; i += 192) sVt[(i / 20) * 104 + 84 + (i % 20)] = 0;

    const __half* qb = g_qkvh + (size_t)b * (NTOK * 768);

    for (int h = 0; h < HEADS; ++h) {
        __syncthreads();   // pad-zero done (h=0) / prev head's reads done
        // ---- cooperative load q,k (16B), v transposed (scalar) ----
        for (int it = tid; it < 1008; it += 192) {
            int s = it / 336, r = it - s * 336;
            int n = r >> 2, c = r & 3;                 // c: which 8-half group
            uint4 v = *reinterpret_cast<const uint4*>(qb + (size_t)n * 768 + s * 256 + h * 32 + c * 8);
            if (s == 0)      *reinterpret_cast<uint4*>(sQ + n * 40 + c * 8) = v;
            else if (s == 1) *reinterpret_cast<uint4*>(sK + n * 40 + c * 8) = v;
            else {
                const unsigned short* pv = reinterpret_cast<const unsigned short*>(&v);
                #pragma unroll
                for (int j = 0; j < 8; ++j)
                    sVt[(c * 8 + j) * 104 + n] = pv[j];
            }
        }
        __syncthreads();

        // ---- S = Q K^T (Q pre-scaled in projection): 24 MMA ----
        float c4[12][4];
        #pragma unroll
        for (int ni = 0; ni < 12; ++ni)
            #pragma unroll
            for (int q = 0; q < 4; ++q) c4[ni][q] = 0.f;

        const int row = w * 16 + g;
        #pragma unroll
        for (int ks = 0; ks < 2; ++ks) {
            uint32_t a[4];
            a[0] = sQw[ row      * 20 + ks * 8 + t];
            a[1] = sQw[(row + 8) * 20 + ks * 8 + t];
            a[2] = sQw[ row      * 20 + ks * 8 + t + 4];
            a[3] = sQw[(row + 8) * 20 + ks * 8 + t + 4];
            #pragma unroll
            for (int ni = 0; ni < 12; ++ni) {
                uint32_t bf[2];
                bf[0] = sKw[(ni * 8 + g) * 20 + ks * 8 + t];
                bf[1] = sKw[(ni * 8 + g) * 20 + ks * 8 + t + 4];
                mma_f16(c4[ni], a, bf);
            }
        }

        // ---- bias + register softmax (rows row, row+8) ----
        const int r0 = row, r1 = row + 8;
        const bool v0r = r0 < NTOK, v1r = r1 < NTOK;
        const float* gb = g_bias + h * (NTOK * NTOK);
        #pragma unroll
        for (int ni = 0; ni < 12; ++ni) {
            int col = ni * 8 + 2 * t;
            if (col < NTOK) {
                if (v0r) {
                    float2 f = *reinterpret_cast<const float2*>(gb + r0 * NTOK + col);
                    c4[ni][0] += f.x; c4[ni][1] += f.y;
                }
                if (v1r) {
                    float2 f = *reinterpret_cast<const float2*>(gb + r1 * NTOK + col);
                    c4[ni][2] += f.x; c4[ni][3] += f.y;
                }
            }
        }
        float m0 = -1e30f, m1 = -1e30f;
        #pragma unroll
        for (int ni = 0; ni < 12; ++ni) {
            int col = ni * 8 + 2 * t;
            if (col < NTOK) {
                m0 = fmaxf(m0, fmaxf(c4[ni][0], c4[ni][1]));
                m1 = fmaxf(m1, fmaxf(c4[ni][2], c4[ni][3]));
            }
        }
        m0 = fmaxf(m0, __shfl_xor_sync(0xffffffffu, m0, 1));
        m0 = fmaxf(m0, __shfl_xor_sync(0xffffffffu, m0, 2));
        m1 = fmaxf(m1, __shfl_xor_sync(0xffffffffu, m1, 1));
        m1 = fmaxf(m1, __shfl_xor_sync(0xffffffffu, m1, 2));
        float s0 = 0.f, s1 = 0.f;
        #pragma unroll
        for (int ni = 0; ni < 12; ++ni) {
            int col = ni * 8 + 2 * t;
            if (col < NTOK) {
                c4[ni][0] = __expf(c4[ni][0] - m0);
                c4[ni][1] = __expf(c4[ni][1] - m0);
                c4[ni][2] = __expf(c4[ni][2] - m1);
                c4[ni][3] = __expf(c4[ni][3] - m1);
                s0 += c4[ni][0] + c4[ni][1];
                s1 += c4[ni][2] + c4[ni][3];
            } else {
                c4[ni][0] = c4[ni][1] = c4[ni][2] = c4[ni][3] = 0.f;
            }
        }
        s0 += __shfl_xor_sync(0xffffffffu, s0, 1);
        s0 += __shfl_xor_sync(0xffffffffu, s0, 2);
        s1 += __shfl_xor_sync(0xffffffffu, s1, 1);
        s1 += __shfl_xor_sync(0xffffffffu, s1, 2);
        const float i0 = 1.f / s0, i1 = 1.f / s1;
        #pragma unroll
        for (int ni = 0; ni < 12; ++ni) {
            c4[ni][0] *= i0; c4[ni][1] *= i0;
            c4[ni][2] *= i1; c4[ni][3] *= i1;
        }

        // ---- PV: P packed from registers (C layout == A layout): 24 MMA ----
        float o[4][4];
        #pragma unroll
        for (int nj = 0; nj < 4; ++nj)
            #pragma unroll
            for (int q = 0; q < 4; ++q) o[nj][q] = 0.f;

        #pragma unroll
        for (int ks = 0; ks < 6; ++ks) {
            uint32_t a[4];
            a[0] = packh2(c4[2 * ks][0],     c4[2 * ks][1]);
            a[1] = packh2(c4[2 * ks][2],     c4[2 * ks][3]);
            a[2] = packh2(c4[2 * ks + 1][0], c4[2 * ks + 1][1]);
            a[3] = packh2(c4[2 * ks + 1][2], c4[2 * ks + 1][3]);
            #pragma unroll
            for (int nj = 0; nj < 4; ++nj) {
                uint32_t bf[2];
                bf[0] = sVw[(nj * 8 + g) * 52 + ks * 8 + t];
                bf[1] = sVw[(nj * 8 + g) * 52 + ks * 8 + t + 4];
                mma_f16(o[nj], a, bf);
            }
        }

        // ---- store fp16 ----
        __half* oa = g_attnh + (size_t)b * (NTOK * 256) + h * 32;
        #pragma unroll
        for (int nj = 0; nj < 4; ++nj) {
            int col = nj * 8 + 2 * t;
            if (v0r)
                *reinterpret_cast<uint32_t*>(oa + (size_t)r0 * 256 + col) =
                    packh2(o[nj][0], o[nj][1]);
            if (v1r)
                *reinterpret_cast<uint32_t*>(oa + (size_t)r1 * 256 + col) =
                    packh2(o[nj][2], o[nj][3]);
        }
    }
}

// ---------------------------------------------------------------------------
extern "C" void kernel_launch(void* const* d_in, const int* in_sizes, int n_in,
                              void* d_out, int out_size)
{
    const float* x     = (const float*)d_in[0];
    const float* Wqkv  = (const float*)d_in[1];
    const float* bqkv  = (const float*)d_in[2];
    const float* Wp    = (const float*)d_in[3];
    const float* bp    = (const float*)d_in[4];
    const float* table = (const float*)d_in[5];
    const int*   ridx  = (const int*)d_in[6];
    float* out = (float*)d_out;

    cudaFuncSetAttribute(gemm_f16_kernel<true>,  cudaFuncAttributeMaxDynamicSharedMemorySize, GEMM_SMEM);
    cudaFuncSetAttribute(gemm_f16_kernel<false>, cudaFuncAttributeMaxDynamicSharedMemorySize, GEMM_SMEM);

    __half* xh;   cudaGetSymbolAddress((void**)&xh,   g_xh);
    __half* qkvh; cudaGetSymbolAddress((void**)&qkvh, g_qkvh);
    __half* ath;  cudaGetSymbolAddress((void**)&ath,  g_attnh);
    __half* wth;  cudaGetSymbolAddress((void**)&wth,  g_WTh);
    __half* wpth; cudaGetSymbolAddress((void**)&wpth, g_WpTh);
    float*  bq;   cudaGetSymbolAddress((void**)&bq,   g_bq);

    // X: MROWS*256 floats = MROWS*64 float4s; 256 thr/blk -> MROWS/4 blocks.
    xprep_kernel<<<MROWS / 4, 256>>>(x);
    wprep_kernel<<<1024, 256>>>(Wqkv, Wp, bqkv);
    bias_kernel<<<28, 256>>>(table, ridx);
    gemm_f16_kernel<true><<<dim3(3, 1344), 512, GEMM_SMEM>>>(xh, wth, bq, qkvh, 768);
    attn_kernel<<<BATCH, 192, ATTN_SMEM>>>();
    gemm_f16_kernel<false><<<dim3(1, 1344), 512, GEMM_SMEM>>>(ath, wpth, bp, out, 256);
}

// round 13
// speedup vs baseline: 2.5304x; 1.1369x over previous
#include <cuda_runtime.h>
#include <cuda_fp16.h>
#include <cstdint>

// Local Scale Attention — round 10: all-fp16 mma.sync. GEMMs with full-K
// 4-stage prefetch (216KB smem, 4 barriers); attention with cp.async +
// ldmatrix.trans V fragments + head double-buffering.
// B=2048, N=84, C=256, H=8, hd=32.

#define BATCH 2048
#define NTOK  84
#define DIM   256
#define HEADS 8
#define MROWS (BATCH * NTOK)            // 172032

__device__ __half g_xh   [(size_t)MROWS * 256];   //  88 MB
__device__ __half g_qkvh [(size_t)MROWS * 768];   // 264 MB
__device__ __half g_attnh[(size_t)MROWS * 256];   //  88 MB
__device__ __half g_WTh  [768 * 256];
__device__ __half g_WpTh [256 * 256];
__device__ float  g_bq   [768];
__device__ float  g_bias [HEADS * NTOK * NTOK];

// ---------------------------------------------------------------------------
__device__ __forceinline__ uint32_t smem_u32(const void* p) {
    uint32_t a;
    asm("{ .reg .u64 t; cvta.to.shared.u64 t, %1; cvt.u32.u64 %0, t; }" : "=r"(a) : "l"(p));
    return a;
}
__device__ __forceinline__ void cp_async16(uint32_t dst, const void* src) {
    asm volatile("cp.async.cg.shared.global [%0], [%1], 16;" :: "r"(dst), "l"(src));
}
__device__ __forceinline__ void mma_f16(float* d, const uint32_t* a, const uint32_t* b) {
    asm volatile(
        "mma.sync.aligned.m16n8k16.row.col.f32.f16.f16.f32 "
        "{%0,%1,%2,%3}, {%4,%5,%6,%7}, {%8,%9}, {%0,%1,%2,%3};"
        : "+f"(d[0]), "+f"(d[1]), "+f"(d[2]), "+f"(d[3])
        : "r"(a[0]), "r"(a[1]), "r"(a[2]), "r"(a[3]), "r"(b[0]), "r"(b[1]));
}
__device__ __forceinline__ uint32_t packh2(float a, float b) {
    __half2 h = __floats2half2_rn(a, b);
    return *reinterpret_cast<uint32_t*>(&h);
}

// ---------------------------------------------------------------------------
// prep kernels
// ---------------------------------------------------------------------------
__global__ void xprep_kernel(const float* __restrict__ x)
{
    size_t i = (size_t)blockIdx.x * 256 + threadIdx.x;   // float4 index
    float4 v = reinterpret_cast<const float4*>(x)[i];
    uint2 u;
    u.x = packh2(v.x, v.y);
    u.y = packh2(v.z, v.w);
    reinterpret_cast<uint2*>(g_xh)[i] = u;
}

__global__ void wprep_kernel(const float* __restrict__ Wqkv, const float* __restrict__ Wp,
                             const float* __restrict__ bqkv)
{
    int n = blockIdx.x, k = threadIdx.x;
    const float s = 0.10910894511799618f;   // 84^-0.5 folded into Q projection
    if (n < 768) {
        float f = (n < 256) ? s : 1.f;
        g_WTh[n * 256 + k] = __float2half_rn(Wqkv[k * 768 + n] * f);
        if (k == 0) g_bq[n] = bqkv[n] * f;
    } else {
        g_WpTh[(n - 768) * 256 + k] = __float2half_rn(Wp[k * 256 + (n - 768)]);
    }
}

__global__ void bias_kernel(const float* __restrict__ table, const int* __restrict__ ridx)
{
    int i = blockIdx.x * blockDim.x + threadIdx.x;
    if (i < NTOK * NTOK) {
        int r = ridx[i];
        #pragma unroll
        for (int h = 0; h < HEADS; ++h)
            g_bias[h * (NTOK * NTOK) + i] = table[r * HEADS + h];
    }
}

// ---------------------------------------------------------------------------
// fp16 GEMM, full-K prefetch: OUT[m][n] = A[m][:256] . BT[n][:256] + bias[n]
// grid (ncols/256, Mrows/128), 512 thr = 16 warps 4(M)x4(N), warp 32x64.
// 4 stages (one per K-chunk of 64) loaded up-front; 4 barriers total.
// stage stride 27648 halves: A [128][72] @0, B [256][72] @9216. 221184 B.
// ---------------------------------------------------------------------------
#define GEMM_SMEM 221184

template<bool OUT_FP16>
__global__ __launch_bounds__(512, 1)
void gemm_f16_kernel(const __half* __restrict__ A, const __half* __restrict__ BT,
                     const float* __restrict__ bias, void* __restrict__ outp, int ncols)
{
    extern __shared__ __half smh[];
    const uint32_t sb = smem_u32(smh);
    const int tid = threadIdx.x;
    const int w = tid >> 5, lane = tid & 31;
    const int g = lane >> 2, t = lane & 3;
    const int wm = w >> 2, wn = w & 3;
    const int n0 = blockIdx.x * 256;
    const int m0 = blockIdx.y * 128;

    const __half* Ab = A + (size_t)m0 * 256;
    const __half* Bb = BT + (size_t)n0 * 256;

    // issue all 4 K-chunks as 4 commit groups
    #pragma unroll
    for (int kc = 0; kc < 4; ++kc) {
        uint32_t ab = sb + kc * (27648 * 2);
        uint32_t bb = ab + 9216 * 2;
        int k0 = kc * 64;
        #pragma unroll
        for (int it = 0; it < 2; ++it) {              // A: 1024 x 16B
            int idx = tid + it * 512;
            int r = idx >> 3, c = idx & 7;
            cp_async16(ab + (r * 72 + c * 8) * 2, Ab + (size_t)r * 256 + k0 + c * 8);
        }
        #pragma unroll
        for (int it = 0; it < 4; ++it) {              // B: 2048 x 16B
            int idx = tid + it * 512;
            int r = idx >> 3, c = idx & 7;
            cp_async16(bb + (r * 72 + c * 8) * 2, Bb + (size_t)r * 256 + k0 + c * 8);
        }
        asm volatile("cp.async.commit_group;" ::: "memory");
    }

    float d[2][8][4];
    #pragma unroll
    for (int i = 0; i < 2; ++i)
        #pragma unroll
        for (int j = 0; j < 8; ++j)
            #pragma unroll
            for (int q = 0; q < 4; ++q) d[i][j][q] = 0.f;

    auto compute = [&](int stage) {
        const uint32_t* sA = reinterpret_cast<const uint32_t*>(smh + stage * 27648);
        const uint32_t* sB = reinterpret_cast<const uint32_t*>(smh + stage * 27648 + 9216);
        #pragma unroll
        for (int ks = 0; ks < 4; ++ks) {              // 4 x k16 = 64
            uint32_t a[2][4], bf[8][2];
            #pragma unroll
            for (int ii = 0; ii < 2; ++ii) {
                int row = wm * 32 + ii * 16 + g;
                a[ii][0] = sA[ row      * 36 + ks * 8 + t];
                a[ii][1] = sA[(row + 8) * 36 + ks * 8 + t];
                a[ii][2] = sA[ row      * 36 + ks * 8 + t + 4];
                a[ii][3] = sA[(row + 8) * 36 + ks * 8 + t + 4];
            }
            #pragma unroll
            for (int j = 0; j < 8; ++j) {
                int n = wn * 64 + j * 8 + g;
                bf[j][0] = sB[n * 36 + ks * 8 + t];
                bf[j][1] = sB[n * 36 + ks * 8 + t + 4];
            }
            #pragma unroll
            for (int ii = 0; ii < 2; ++ii)
                #pragma unroll
                for (int j = 0; j < 8; ++j)
                    mma_f16(d[ii][j], a[ii], bf[j]);
        }
    };

    asm volatile("cp.async.wait_group 3;" ::: "memory"); __syncthreads(); compute(0);
    asm volatile("cp.async.wait_group 2;" ::: "memory"); __syncthreads(); compute(1);
    asm volatile("cp.async.wait_group 1;" ::: "memory"); __syncthreads(); compute(2);
    asm volatile("cp.async.wait_group 0;" ::: "memory"); __syncthreads(); compute(3);

    #pragma unroll
    for (int ii = 0; ii < 2; ++ii) {
        int row = m0 + wm * 32 + ii * 16 + g;
        #pragma unroll
        for (int j = 0; j < 8; ++j) {
            int col = n0 + wn * 64 + j * 8 + 2 * t;
            float b0 = bias[col], b1 = bias[col + 1];
            if (OUT_FP16) {
                __half* oh = reinterpret_cast<__half*>(outp);
                uint32_t v0 = packh2(d[ii][j][0] + b0, d[ii][j][1] + b1);
                uint32_t v1 = packh2(d[ii][j][2] + b0, d[ii][j][3] + b1);
                *reinterpret_cast<uint32_t*>(oh + (size_t)row * ncols + col) = v0;
                *reinterpret_cast<uint32_t*>(oh + (size_t)(row + 8) * ncols + col) = v1;
            } else {
                float* of = reinterpret_cast<float*>(outp);
                *reinterpret_cast<float2*>(of + (size_t)row * ncols + col) =
                    make_float2(d[ii][j][0] + b0, d[ii][j][1] + b1);
                *reinterpret_cast<float2*>(of + (size_t)(row + 8) * ncols + col) =
                    make_float2(d[ii][j][2] + b0, d[ii][j][3] + b1);
            }
        }
    }
}

// ---------------------------------------------------------------------------
// attention: grid=2048, 192 threads (6 warps), warp owns 16 q-rows.
// Register softmax; V consumed via ldmatrix.x4.trans (B-fragment of
// V[key][dim] rows); Q/K/V all cp.async; heads double-buffered.
// smem per buffer: Q[96][40] K[96][40] V[96][40] = 11520 halves; x2 = 46080 B.
// 4 CTA/SM.
// ---------------------------------------------------------------------------
#define ATTN_BUF 11520
#define ATTN_SMEM (2 * ATTN_BUF * 2)

__global__ __launch_bounds__(192, 4)
void attn_kernel()
{
    extern __shared__ __half smh[];
    const uint32_t sb = smem_u32(smh);
    const int tid = threadIdx.x;
    const int w = tid >> 5, l = tid & 31;
    const int g = l >> 2, t = l & 3;
    const int b = blockIdx.x;

    // zero V pad rows (keys 84..95) in both buffers once: P there is 0, but
    // garbage could be NaN and 0*NaN = NaN.
    for (int i = tid; i < 480; i += 192) {
        int off = 7680 + (84 + i / 40) * 40 + (i % 40);
        smh[off] = __ushort_as_half(0);
        smh[ATTN_BUF + off] = __ushort_as_half(0);
    }

    const __half* qb = g_qkvh + (size_t)b * (NTOK * 768);

    auto issue_load = [&](int h, int buf) {
        uint32_t base = sb + buf * (ATTN_BUF * 2);
        const __half* src = qb + h * 32;
        for (int it = tid; it < 1008; it += 192) {
            int s = it / 336, r = it - s * 336;
            int n = r >> 2, c = r & 3;
            cp_async16(base + (s * 3840 + n * 40 + c * 8) * 2,
                       src + (size_t)n * 768 + s * 256 + c * 8);
        }
        asm volatile("cp.async.commit_group;" ::: "memory");
    };

    issue_load(0, 0);
    int buf = 0;

    for (int h = 0; h < HEADS; ++h) {
        if (h + 1 < HEADS) {
            issue_load(h + 1, buf ^ 1);            // WAR-safe: barrier at end of prev iter
            asm volatile("cp.async.wait_group 1;" ::: "memory");
        } else {
            asm volatile("cp.async.wait_group 0;" ::: "memory");
        }
        __syncthreads();                           // publish buf h (+ pad zeroing on h=0)

        const uint32_t* sQw = reinterpret_cast<const uint32_t*>(smh + buf * ATTN_BUF);
        const uint32_t* sKw = reinterpret_cast<const uint32_t*>(smh + buf * ATTN_BUF + 3840);
        const uint32_t svb = sb + (buf * ATTN_BUF + 7680) * 2;

        // ---- S = Q K^T (Q pre-scaled in projection): 24 MMA ----
        float c4[12][4];
        #pragma unroll
        for (int ni = 0; ni < 12; ++ni)
            #pragma unroll
            for (int q = 0; q < 4; ++q) c4[ni][q] = 0.f;

        const int row = w * 16 + g;
        #pragma unroll
        for (int ks = 0; ks < 2; ++ks) {
            uint32_t a[4];
            a[0] = sQw[ row      * 20 + ks * 8 + t];
            a[1] = sQw[(row + 8) * 20 + ks * 8 + t];
            a[2] = sQw[ row      * 20 + ks * 8 + t + 4];
            a[3] = sQw[(row + 8) * 20 + ks * 8 + t + 4];
            #pragma unroll
            for (int ni = 0; ni < 12; ++ni) {
                uint32_t bf[2];
                bf[0] = sKw[(ni * 8 + g) * 20 + ks * 8 + t];
                bf[1] = sKw[(ni * 8 + g) * 20 + ks * 8 + t + 4];
                mma_f16(c4[ni], a, bf);
            }
        }

        // ---- bias + register softmax (rows row, row+8) ----
        const int r0 = row, r1 = row + 8;
        const bool v0r = r0 < NTOK, v1r = r1 < NTOK;
        const float* gb = g_bias + h * (NTOK * NTOK);
        #pragma unroll
        for (int ni = 0; ni < 12; ++ni) {
            int col = ni * 8 + 2 * t;
            if (col < NTOK) {
                if (v0r) {
                    float2 f = *reinterpret_cast<const float2*>(gb + r0 * NTOK + col);
                    c4[ni][0] += f.x; c4[ni][1] += f.y;
                }
                if (v1r) {
                    float2 f = *reinterpret_cast<const float2*>(gb + r1 * NTOK + col);
                    c4[ni][2] += f.x; c4[ni][3] += f.y;
                }
            }
        }
        float m0 = -1e30f, m1 = -1e30f;
        #pragma unroll
        for (int ni = 0; ni < 12; ++ni) {
            int col = ni * 8 + 2 * t;
            if (col < NTOK) {
                m0 = fmaxf(m0, fmaxf(c4[ni][0], c4[ni][1]));
                m1 = fmaxf(m1, fmaxf(c4[ni][2], c4[ni][3]));
            }
        }
        m0 = fmaxf(m0, __shfl_xor_sync(0xffffffffu, m0, 1));
        m0 = fmaxf(m0, __shfl_xor_sync(0xffffffffu, m0, 2));
        m1 = fmaxf(m1, __shfl_xor_sync(0xffffffffu, m1, 1));
        m1 = fmaxf(m1, __shfl_xor_sync(0xffffffffu, m1, 2));
        float s0 = 0.f, s1 = 0.f;
        #pragma unroll
        for (int ni = 0; ni < 12; ++ni) {
            int col = ni * 8 + 2 * t;
            if (col < NTOK) {
                c4[ni][0] = __expf(c4[ni][0] - m0);
                c4[ni][1] = __expf(c4[ni][1] - m0);
                c4[ni][2] = __expf(c4[ni][2] - m1);
                c4[ni][3] = __expf(c4[ni][3] - m1);
                s0 += c4[ni][0] + c4[ni][1];
                s1 += c4[ni][2] + c4[ni][3];
            } else {
                c4[ni][0] = c4[ni][1] = c4[ni][2] = c4[ni][3] = 0.f;
            }
        }
        s0 += __shfl_xor_sync(0xffffffffu, s0, 1);
        s0 += __shfl_xor_sync(0xffffffffu, s0, 2);
        s1 += __shfl_xor_sync(0xffffffffu, s1, 1);
        s1 += __shfl_xor_sync(0xffffffffu, s1, 2);
        const float i0 = 1.f / s0, i1 = 1.f / s1;
        #pragma unroll
        for (int ni = 0; ni < 12; ++ni) {
            c4[ni][0] *= i0; c4[ni][1] *= i0;
            c4[ni][2] *= i1; c4[ni][3] *= i1;
        }

        // ---- PV: A from registers; B via ldmatrix.x4.trans on V rows ----
        float o[4][4];
        #pragma unroll
        for (int nj = 0; nj < 4; ++nj)
            #pragma unroll
            for (int q = 0; q < 4; ++q) o[nj][q] = 0.f;

        #pragma unroll
        for (int ks = 0; ks < 6; ++ks) {
            uint32_t a[4];
            a[0] = packh2(c4[2 * ks][0],     c4[2 * ks][1]);
            a[1] = packh2(c4[2 * ks][2],     c4[2 * ks][3]);
            a[2] = packh2(c4[2 * ks + 1][0], c4[2 * ks + 1][1]);
            a[3] = packh2(c4[2 * ks + 1][2], c4[2 * ks + 1][3]);
            #pragma unroll
            for (int njp = 0; njp < 2; ++njp) {
                uint32_t r0m, r1m, r2m, r3m;
                uint32_t addr = svb +
                    (((ks * 16 + (l & 15)) * 40) + (njp * 2 + (l >> 4)) * 8) * 2;
                asm volatile(
                    "ldmatrix.sync.aligned.m8n8.x4.trans.shared.b16 {%0,%1,%2,%3}, [%4];"
                    : "=r"(r0m), "=r"(r1m), "=r"(r2m), "=r"(r3m) : "r"(addr));
                uint32_t bf0[2] = {r0m, r1m};
                uint32_t bf1[2] = {r2m, r3m};
                mma_f16(o[njp * 2],     a, bf0);
                mma_f16(o[njp * 2 + 1], a, bf1);
            }
        }

        // ---- store fp16 ----
        __half* oa = g_attnh + (size_t)b * (NTOK * 256) + h * 32;
        #pragma unroll
        for (int nj = 0; nj < 4; ++nj) {
            int col = nj * 8 + 2 * t;
            if (v0r)
                *reinterpret_cast<uint32_t*>(oa + (size_t)r0 * 256 + col) =
                    packh2(o[nj][0], o[nj][1]);
            if (v1r)
                *reinterpret_cast<uint32_t*>(oa + (size_t)r1 * 256 + col) =
                    packh2(o[nj][2], o[nj][3]);
        }

        __syncthreads();                           // all reads of buf h done (WAR)
        buf ^= 1;
    }
}

// ---------------------------------------------------------------------------
extern "C" void kernel_launch(void* const* d_in, const int* in_sizes, int n_in,
                              void* d_out, int out_size)
{
    const float* x     = (const float*)d_in[0];
    const float* Wqkv  = (const float*)d_in[1];
    const float* bqkv  = (const float*)d_in[2];
    const float* Wp    = (const float*)d_in[3];
    const float* bp    = (const float*)d_in[4];
    const float* table = (const float*)d_in[5];
    const int*   ridx  = (const int*)d_in[6];
    float* out = (float*)d_out;

    cudaFuncSetAttribute(gemm_f16_kernel<true>,  cudaFuncAttributeMaxDynamicSharedMemorySize, GEMM_SMEM);
    cudaFuncSetAttribute(gemm_f16_kernel<false>, cudaFuncAttributeMaxDynamicSharedMemorySize, GEMM_SMEM);
    cudaFuncSetAttribute(attn_kernel, cudaFuncAttributeMaxDynamicSharedMemorySize, ATTN_SMEM);

    __half* xh;   cudaGetSymbolAddress((void**)&xh,   g_xh);
    __half* qkvh; cudaGetSymbolAddress((void**)&qkvh, g_qkvh);
    __half* ath;  cudaGetSymbolAddress((void**)&ath,  g_attnh);
    __half* wth;  cudaGetSymbolAddress((void**)&wth,  g_WTh);
    __half* wpth; cudaGetSymbolAddress((void**)&wpth, g_WpTh);
    float*  bq;   cudaGetSymbolAddress((void**)&bq,   g_bq);

    // X: MROWS*256 floats = MROWS*64 float4s; 256 thr/blk -> MROWS/4 blocks.
    xprep_kernel<<<MROWS / 4, 256>>>(x);
    wprep_kernel<<<1024, 256>>>(Wqkv, Wp, bqkv);
    bias_kernel<<<28, 256>>>(table, ridx);
    gemm_f16_kernel<true><<<dim3(3, 1344), 512, GEMM_SMEM>>>(xh, wth, bq, qkvh, 768);
    attn_kernel<<<BATCH, 192, ATTN_SMEM>>>();
    gemm_f16_kernel<false><<<dim3(1, 1344), 512, GEMM_SMEM>>>(ath, wpth, bp, out, 256);
}

// round 14
// speedup vs baseline: 2.5646x; 1.0135x over previous
#include <cuda_runtime.h>
#include <cuda_fp16.h>
#include <cstdint>

// Local Scale Attention — round 11: round 10 + ldmatrix fragment loads in the
// GEMMs (96 scalar LDS -> 24 LDSM.x4 per warp per K-stage).
// B=2048, N=84, C=256, H=8, hd=32.

#define BATCH 2048
#define NTOK  84
#define DIM   256
#define HEADS 8
#define MROWS (BATCH * NTOK)            // 172032

__device__ __half g_xh   [(size_t)MROWS * 256];   //  88 MB
__device__ __half g_qkvh [(size_t)MROWS * 768];   // 264 MB
__device__ __half g_attnh[(size_t)MROWS * 256];   //  88 MB
__device__ __half g_WTh  [768 * 256];
__device__ __half g_WpTh [256 * 256];
__device__ float  g_bq   [768];
__device__ float  g_bias [HEADS * NTOK * NTOK];

// ---------------------------------------------------------------------------
__device__ __forceinline__ uint32_t smem_u32(const void* p) {
    uint32_t a;
    asm("{ .reg .u64 t; cvta.to.shared.u64 t, %1; cvt.u32.u64 %0, t; }" : "=r"(a) : "l"(p));
    return a;
}
__device__ __forceinline__ void cp_async16(uint32_t dst, const void* src) {
    asm volatile("cp.async.cg.shared.global [%0], [%1], 16;" :: "r"(dst), "l"(src));
}
__device__ __forceinline__ void mma_f16(float* d, const uint32_t* a, const uint32_t* b) {
    asm volatile(
        "mma.sync.aligned.m16n8k16.row.col.f32.f16.f16.f32 "
        "{%0,%1,%2,%3}, {%4,%5,%6,%7}, {%8,%9}, {%0,%1,%2,%3};"
        : "+f"(d[0]), "+f"(d[1]), "+f"(d[2]), "+f"(d[3])
        : "r"(a[0]), "r"(a[1]), "r"(a[2]), "r"(a[3]), "r"(b[0]), "r"(b[1]));
}
__device__ __forceinline__ uint32_t packh2(float a, float b) {
    __half2 h = __floats2half2_rn(a, b);
    return *reinterpret_cast<uint32_t*>(&h);
}

// ---------------------------------------------------------------------------
// prep kernels
// ---------------------------------------------------------------------------
__global__ void xprep_kernel(const float* __restrict__ x)
{
    size_t i = (size_t)blockIdx.x * 256 + threadIdx.x;   // float4 index
    float4 v = reinterpret_cast<const float4*>(x)[i];
    uint2 u;
    u.x = packh2(v.x, v.y);
    u.y = packh2(v.z, v.w);
    reinterpret_cast<uint2*>(g_xh)[i] = u;
}

__global__ void wprep_kernel(const float* __restrict__ Wqkv, const float* __restrict__ Wp,
                             const float* __restrict__ bqkv)
{
    int n = blockIdx.x, k = threadIdx.x;
    const float s = 0.10910894511799618f;   // 84^-0.5 folded into Q projection
    if (n < 768) {
        float f = (n < 256) ? s : 1.f;
        g_WTh[n * 256 + k] = __float2half_rn(Wqkv[k * 768 + n] * f);
        if (k == 0) g_bq[n] = bqkv[n] * f;
    } else {
        g_WpTh[(n - 768) * 256 + k] = __float2half_rn(Wp[k * 256 + (n - 768)]);
    }
}

__global__ void bias_kernel(const float* __restrict__ table, const int* __restrict__ ridx)
{
    int i = blockIdx.x * blockDim.x + threadIdx.x;
    if (i < NTOK * NTOK) {
        int r = ridx[i];
        #pragma unroll
        for (int h = 0; h < HEADS; ++h)
            g_bias[h * (NTOK * NTOK) + i] = table[r * HEADS + h];
    }
}

// ---------------------------------------------------------------------------
// fp16 GEMM, full-K prefetch + ldmatrix fragment loads.
// grid (ncols/256, Mrows/128), 512 thr = 16 warps 4(M)x4(N), warp 32x64.
// 4 stages loaded up-front; stage stride 27648 halves: A[128][72] B[256][72].
// ---------------------------------------------------------------------------
#define GEMM_SMEM 221184

template<bool OUT_FP16>
__global__ __launch_bounds__(512, 1)
void gemm_f16_kernel(const __half* __restrict__ A, const __half* __restrict__ BT,
                     const float* __restrict__ bias, void* __restrict__ outp, int ncols)
{
    extern __shared__ __half smh[];
    const uint32_t sb = smem_u32(smh);
    const int tid = threadIdx.x;
    const int w = tid >> 5, lane = tid & 31;
    const int g = lane >> 2, t = lane & 3;
    const int wm = w >> 2, wn = w & 3;
    const int n0 = blockIdx.x * 256;
    const int m0 = blockIdx.y * 128;

    const __half* Ab = A + (size_t)m0 * 256;
    const __half* Bb = BT + (size_t)n0 * 256;

    // issue all 4 K-chunks as 4 commit groups
    #pragma unroll
    for (int kc = 0; kc < 4; ++kc) {
        uint32_t ab = sb + kc * (27648 * 2);
        uint32_t bb = ab + 9216 * 2;
        int k0 = kc * 64;
        #pragma unroll
        for (int it = 0; it < 2; ++it) {              // A: 1024 x 16B
            int idx = tid + it * 512;
            int r = idx >> 3, c = idx & 7;
            cp_async16(ab + (r * 72 + c * 8) * 2, Ab + (size_t)r * 256 + k0 + c * 8);
        }
        #pragma unroll
        for (int it = 0; it < 4; ++it) {              // B: 2048 x 16B
            int idx = tid + it * 512;
            int r = idx >> 3, c = idx & 7;
            cp_async16(bb + (r * 72 + c * 8) * 2, Bb + (size_t)r * 256 + k0 + c * 8);
        }
        asm volatile("cp.async.commit_group;" ::: "memory");
    }

    float d[2][8][4];
    #pragma unroll
    for (int i = 0; i < 2; ++i)
        #pragma unroll
        for (int j = 0; j < 8; ++j)
            #pragma unroll
            for (int q = 0; q < 4; ++q) d[i][j][q] = 0.f;

    // ldmatrix lane-address components (constant across stages)
    const int arow  = lane & 15;                 // A: rows (l&15), koff (l>>4)*8
    const int akoff = (lane >> 4) * 8;
    const int bnrow = ((lane >> 4) << 3) + (lane & 7);   // B: n rows
    const int bkoff = ((lane >> 3) & 1) * 8;

    auto compute = [&](int stage) {
        const uint32_t sAb = sb + stage * (27648 * 2);
        const uint32_t sBb = sAb + 9216 * 2;
        #pragma unroll
        for (int ks = 0; ks < 4; ++ks) {              // 4 x k16 = 64
            uint32_t a[2][4], bf[8][2];
            #pragma unroll
            for (int ii = 0; ii < 2; ++ii) {
                int row = wm * 32 + ii * 16 + arow;
                uint32_t addr = sAb + (row * 72 + ks * 16 + akoff) * 2;
                asm volatile(
                    "ldmatrix.sync.aligned.m8n8.x4.shared.b16 {%0,%1,%2,%3}, [%4];"
                    : "=r"(a[ii][0]), "=r"(a[ii][1]), "=r"(a[ii][2]), "=r"(a[ii][3])
                    : "r"(addr));
            }
            #pragma unroll
            for (int jp = 0; jp < 4; ++jp) {
                int n = wn * 64 + jp * 16 + bnrow;
                uint32_t addr = sBb + (n * 72 + ks * 16 + bkoff) * 2;
                asm volatile(
                    "ldmatrix.sync.aligned.m8n8.x4.shared.b16 {%0,%1,%2,%3}, [%4];"
                    : "=r"(bf[2 * jp][0]), "=r"(bf[2 * jp][1]),
                      "=r"(bf[2 * jp + 1][0]), "=r"(bf[2 * jp + 1][1])
                    : "r"(addr));
            }
            #pragma unroll
            for (int ii = 0; ii < 2; ++ii)
                #pragma unroll
                for (int j = 0; j < 8; ++j)
                    mma_f16(d[ii][j], a[ii], bf[j]);
        }
    };

    asm volatile("cp.async.wait_group 3;" ::: "memory"); __syncthreads(); compute(0);
    asm volatile("cp.async.wait_group 2;" ::: "memory"); __syncthreads(); compute(1);
    asm volatile("cp.async.wait_group 1;" ::: "memory"); __syncthreads(); compute(2);
    asm volatile("cp.async.wait_group 0;" ::: "memory"); __syncthreads(); compute(3);

    #pragma unroll
    for (int ii = 0; ii < 2; ++ii) {
        int row = m0 + wm * 32 + ii * 16 + g;
        #pragma unroll
        for (int j = 0; j < 8; ++j) {
            int col = n0 + wn * 64 + j * 8 + 2 * t;
            float b0 = bias[col], b1 = bias[col + 1];
            if (OUT_FP16) {
                __half* oh = reinterpret_cast<__half*>(outp);
                uint32_t v0 = packh2(d[ii][j][0] + b0, d[ii][j][1] + b1);
                uint32_t v1 = packh2(d[ii][j][2] + b0, d[ii][j][3] + b1);
                *reinterpret_cast<uint32_t*>(oh + (size_t)row * ncols + col) = v0;
                *reinterpret_cast<uint32_t*>(oh + (size_t)(row + 8) * ncols + col) = v1;
            } else {
                float* of = reinterpret_cast<float*>(outp);
                *reinterpret_cast<float2*>(of + (size_t)row * ncols + col) =
                    make_float2(d[ii][j][0] + b0, d[ii][j][1] + b1);
                *reinterpret_cast<float2*>(of + (size_t)(row + 8) * ncols + col) =
                    make_float2(d[ii][j][2] + b0, d[ii][j][3] + b1);
            }
        }
    }
}

// ---------------------------------------------------------------------------
// attention (unchanged from round 10): 192 thr, register softmax,
// ldmatrix.trans V, head double-buffering, 4 CTA/SM.
// ---------------------------------------------------------------------------
#define ATTN_BUF 11520
#define ATTN_SMEM (2 * ATTN_BUF * 2)

__global__ __launch_bounds__(192, 4)
void attn_kernel()
{
    extern __shared__ __half smh[];
    const uint32_t sb = smem_u32(smh);
    const int tid = threadIdx.x;
    const int w = tid >> 5, l = tid & 31;
    const int g = l >> 2, t = l & 3;
    const int b = blockIdx.x;

    for (int i = tid; i < 480; i += 192) {
        int off = 7680 + (84 + i / 40) * 40 + (i % 40);
        smh[off] = __ushort_as_half(0);
        smh[ATTN_BUF + off] = __ushort_as_half(0);
    }

    const __half* qb = g_qkvh + (size_t)b * (NTOK * 768);

    auto issue_load = [&](int h, int buf) {
        uint32_t base = sb + buf * (ATTN_BUF * 2);
        const __half* src = qb + h * 32;
        for (int it = tid; it < 1008; it += 192) {
            int s = it / 336, r = it - s * 336;
            int n = r >> 2, c = r & 3;
            cp_async16(base + (s * 3840 + n * 40 + c * 8) * 2,
                       src + (size_t)n * 768 + s * 256 + c * 8);
        }
        asm volatile("cp.async.commit_group;" ::: "memory");
    };

    issue_load(0, 0);
    int buf = 0;

    for (int h = 0; h < HEADS; ++h) {
        if (h + 1 < HEADS) {
            issue_load(h + 1, buf ^ 1);
            asm volatile("cp.async.wait_group 1;" ::: "memory");
        } else {
            asm volatile("cp.async.wait_group 0;" ::: "memory");
        }
        __syncthreads();

        const uint32_t* sQw = reinterpret_cast<const uint32_t*>(smh + buf * ATTN_BUF);
        const uint32_t* sKw = reinterpret_cast<const uint32_t*>(smh + buf * ATTN_BUF + 3840);
        const uint32_t svb = sb + (buf * ATTN_BUF + 7680) * 2;

        float c4[12][4];
        #pragma unroll
        for (int ni = 0; ni < 12; ++ni)
            #pragma unroll
            for (int q = 0; q < 4; ++q) c4[ni][q] = 0.f;

        const int row = w * 16 + g;
        #pragma unroll
        for (int ks = 0; ks < 2; ++ks) {
            uint32_t a[4];
            a[0] = sQw[ row      * 20 + ks * 8 + t];
            a[1] = sQw[(row + 8) * 20 + ks * 8 + t];
            a[2] = sQw[ row      * 20 + ks * 8 + t + 4];
            a[3] = sQw[(row + 8) * 20 + ks * 8 + t + 4];
            #pragma unroll
            for (int ni = 0; ni < 12; ++ni) {
                uint32_t bf[2];
                bf[0] = sKw[(ni * 8 + g) * 20 + ks * 8 + t];
                bf[1] = sKw[(ni * 8 + g) * 20 + ks * 8 + t + 4];
                mma_f16(c4[ni], a, bf);
            }
        }

        const int r0 = row, r1 = row + 8;
        const bool v0r = r0 < NTOK, v1r = r1 < NTOK;
        const float* gb = g_bias + h * (NTOK * NTOK);
        #pragma unroll
        for (int ni = 0; ni < 12; ++ni) {
            int col = ni * 8 + 2 * t;
            if (col < NTOK) {
                if (v0r) {
                    float2 f = *reinterpret_cast<const float2*>(gb + r0 * NTOK + col);
                    c4[ni][0] += f.x; c4[ni][1] += f.y;
                }
                if (v1r) {
                    float2 f = *reinterpret_cast<const float2*>(gb + r1 * NTOK + col);
                    c4[ni][2] += f.x; c4[ni][3] += f.y;
                }
            }
        }
        float m0 = -1e30f, m1 = -1e30f;
        #pragma unroll
        for (int ni = 0; ni < 12; ++ni) {
            int col = ni * 8 + 2 * t;
            if (col < NTOK) {
                m0 = fmaxf(m0, fmaxf(c4[ni][0], c4[ni][1]));
                m1 = fmaxf(m1, fmaxf(c4[ni][2], c4[ni][3]));
            }
        }
        m0 = fmaxf(m0, __shfl_xor_sync(0xffffffffu, m0, 1));
        m0 = fmaxf(m0, __shfl_xor_sync(0xffffffffu, m0, 2));
        m1 = fmaxf(m1, __shfl_xor_sync(0xffffffffu, m1, 1));
        m1 = fmaxf(m1, __shfl_xor_sync(0xffffffffu, m1, 2));
        float s0 = 0.f, s1 = 0.f;
        #pragma unroll
        for (int ni = 0; ni < 12; ++ni) {
            int col = ni * 8 + 2 * t;
            if (col < NTOK) {
                c4[ni][0] = __expf(c4[ni][0] - m0);
                c4[ni][1] = __expf(c4[ni][1] - m0);
                c4[ni][2] = __expf(c4[ni][2] - m1);
                c4[ni][3] = __expf(c4[ni][3] - m1);
                s0 += c4[ni][0] + c4[ni][1];
                s1 += c4[ni][2] + c4[ni][3];
            } else {
                c4[ni][0] = c4[ni][1] = c4[ni][2] = c4[ni][3] = 0.f;
            }
        }
        s0 += __shfl_xor_sync(0xffffffffu, s0, 1);
        s0 += __shfl_xor_sync(0xffffffffu, s0, 2);
        s1 += __shfl_xor_sync(0xffffffffu, s1, 1);
        s1 += __shfl_xor_sync(0xffffffffu, s1, 2);
        const float i0 = 1.f / s0, i1 = 1.f / s1;
        #pragma unroll
        for (int ni = 0; ni < 12; ++ni) {
            c4[ni][0] *= i0; c4[ni][1] *= i0;
            c4[ni][2] *= i1; c4[ni][3] *= i1;
        }

        float o[4][4];
        #pragma unroll
        for (int nj = 0; nj < 4; ++nj)
            #pragma unroll
            for (int q = 0; q < 4; ++q) o[nj][q] = 0.f;

        #pragma unroll
        for (int ks = 0; ks < 6; ++ks) {
            uint32_t a[4];
            a[0] = packh2(c4[2 * ks][0],     c4[2 * ks][1]);
            a[1] = packh2(c4[2 * ks][2],     c4[2 * ks][3]);
            a[2] = packh2(c4[2 * ks + 1][0], c4[2 * ks + 1][1]);
            a[3] = packh2(c4[2 * ks + 1][2], c4[2 * ks + 1][3]);
            #pragma unroll
            for (int njp = 0; njp < 2; ++njp) {
                uint32_t r0m, r1m, r2m, r3m;
                uint32_t addr = svb +
                    (((ks * 16 + (l & 15)) * 40) + (njp * 2 + (l >> 4)) * 8) * 2;
                asm volatile(
                    "ldmatrix.sync.aligned.m8n8.x4.trans.shared.b16 {%0,%1,%2,%3}, [%4];"
                    : "=r"(r0m), "=r"(r1m), "=r"(r2m), "=r"(r3m) : "r"(addr));
                uint32_t bf0[2] = {r0m, r1m};
                uint32_t bf1[2] = {r2m, r3m};
                mma_f16(o[njp * 2],     a, bf0);
                mma_f16(o[njp * 2 + 1], a, bf1);
            }
        }

        __half* oa = g_attnh + (size_t)b * (NTOK * 256) + h * 32;
        #pragma unroll
        for (int nj = 0; nj < 4; ++nj) {
            int col = nj * 8 + 2 * t;
            if (v0r)
                *reinterpret_cast<uint32_t*>(oa + (size_t)r0 * 256 + col) =
                    packh2(o[nj][0], o[nj][1]);
            if (v1r)
                *reinterpret_cast<uint32_t*>(oa + (size_t)r1 * 256 + col) =
                    packh2(o[nj][2], o[nj][3]);
        }

        __syncthreads();
        buf ^= 1;
    }
}

// ---------------------------------------------------------------------------
extern "C" void kernel_launch(void* const* d_in, const int* in_sizes, int n_in,
                              void* d_out, int out_size)
{
    const float* x     = (const float*)d_in[0];
    const float* Wqkv  = (const float*)d_in[1];
    const float* bqkv  = (const float*)d_in[2];
    const float* Wp    = (const float*)d_in[3];
    const float* bp    = (const float*)d_in[4];
    const float* table = (const float*)d_in[5];
    const int*   ridx  = (const int*)d_in[6];
    float* out = (float*)d_out;

    cudaFuncSetAttribute(gemm_f16_kernel<true>,  cudaFuncAttributeMaxDynamicSharedMemorySize, GEMM_SMEM);
    cudaFuncSetAttribute(gemm_f16_kernel<false>, cudaFuncAttributeMaxDynamicSharedMemorySize, GEMM_SMEM);
    cudaFuncSetAttribute(attn_kernel, cudaFuncAttributeMaxDynamicSharedMemorySize, ATTN_SMEM);

    __half* xh;   cudaGetSymbolAddress((void**)&xh,   g_xh);
    __half* qkvh; cudaGetSymbolAddress((void**)&qkvh, g_qkvh);
    __half* ath;  cudaGetSymbolAddress((void**)&ath,  g_attnh);
    __half* wth;  cudaGetSymbolAddress((void**)&wth,  g_WTh);
    __half* wpth; cudaGetSymbolAddress((void**)&wpth, g_WpTh);
    float*  bq;   cudaGetSymbolAddress((void**)&bq,   g_bq);

    xprep_kernel<<<MROWS / 4, 256>>>(x);
    wprep_kernel<<<1024, 256>>>(Wqkv, Wp, bqkv);
    bias_kernel<<<28, 256>>>(table, ridx);
    gemm_f16_kernel<true><<<dim3(3, 1344), 512, GEMM_SMEM>>>(xh, wth, bq, qkvh, 768);
    attn_kernel<<<BATCH, 192, ATTN_SMEM>>>();
    gemm_f16_kernel<false><<<dim3(1, 1344), 512, GEMM_SMEM>>>(ath, wpth, bp, out, 256);
}

// round 16
// speedup vs baseline: 2.7157x; 1.0589x over previous
#include <cuda_runtime.h>
#include <cuda_fp16.h>
#include <cstdint>

// Local Scale Attention — round 13: GEMM = 256-thr 128x128 CTA (2 CTA/SM)
// driven by the PROVEN 2-stage double-buffer loop (round-9 structure).
// Attention unchanged. B=2048, N=84, C=256, H=8, hd=32.

#define BATCH 2048
#define NTOK  84
#define DIM   256
#define HEADS 8
#define MROWS (BATCH * NTOK)            // 172032

__device__ __half g_xh   [(size_t)MROWS * 256];   //  88 MB
__device__ __half g_qkvh [(size_t)MROWS * 768];   // 264 MB
__device__ __half g_attnh[(size_t)MROWS * 256];   //  88 MB
__device__ __half g_WTh  [768 * 256];
__device__ __half g_WpTh [256 * 256];
__device__ float  g_bq   [768];
__device__ float  g_bias [HEADS * NTOK * NTOK];

// ---------------------------------------------------------------------------
__device__ __forceinline__ uint32_t smem_u32(const void* p) {
    uint32_t a;
    asm("{ .reg .u64 t; cvta.to.shared.u64 t, %1; cvt.u32.u64 %0, t; }" : "=r"(a) : "l"(p));
    return a;
}
__device__ __forceinline__ void cp_async16(uint32_t dst, const void* src) {
    asm volatile("cp.async.cg.shared.global [%0], [%1], 16;" :: "r"(dst), "l"(src));
}
__device__ __forceinline__ void mma_f16(float* d, const uint32_t* a, const uint32_t* b) {
    asm volatile(
        "mma.sync.aligned.m16n8k16.row.col.f32.f16.f16.f32 "
        "{%0,%1,%2,%3}, {%4,%5,%6,%7}, {%8,%9}, {%0,%1,%2,%3};"
        : "+f"(d[0]), "+f"(d[1]), "+f"(d[2]), "+f"(d[3])
        : "r"(a[0]), "r"(a[1]), "r"(a[2]), "r"(a[3]), "r"(b[0]), "r"(b[1]));
}
__device__ __forceinline__ uint32_t packh2(float a, float b) {
    __half2 h = __floats2half2_rn(a, b);
    return *reinterpret_cast<uint32_t*>(&h);
}

// ---------------------------------------------------------------------------
// prep kernels
// ---------------------------------------------------------------------------
__global__ void xprep_kernel(const float* __restrict__ x)
{
    size_t i = (size_t)blockIdx.x * 256 + threadIdx.x;   // float4 index
    float4 v = reinterpret_cast<const float4*>(x)[i];
    uint2 u;
    u.x = packh2(v.x, v.y);
    u.y = packh2(v.z, v.w);
    reinterpret_cast<uint2*>(g_xh)[i] = u;
}

__global__ void wprep_kernel(const float* __restrict__ Wqkv, const float* __restrict__ Wp,
                             const float* __restrict__ bqkv)
{
    int n = blockIdx.x, k = threadIdx.x;
    const float s = 0.10910894511799618f;   // 84^-0.5 folded into Q projection
    if (n < 768) {
        float f = (n < 256) ? s : 1.f;
        g_WTh[n * 256 + k] = __float2half_rn(Wqkv[k * 768 + n] * f);
        if (k == 0) g_bq[n] = bqkv[n] * f;
    } else {
        g_WpTh[(n - 768) * 256 + k] = __float2half_rn(Wp[k * 256 + (n - 768)]);
    }
}

__global__ void bias_kernel(const float* __restrict__ table, const int* __restrict__ ridx)
{
    int i = blockIdx.x * blockDim.x + threadIdx.x;
    if (i < NTOK * NTOK) {
        int r = ridx[i];
        #pragma unroll
        for (int h = 0; h < HEADS; ++h)
            g_bias[h * (NTOK * NTOK) + i] = table[r * HEADS + h];
    }
}

// ---------------------------------------------------------------------------
// fp16 GEMM: 256 thr, CTA tile 128x128 (8 warps 4Mx2N, warp 32x64),
// K=256 as 4 chunks of 64, classic 2-stage double buffer (round-9 loop).
// stage: A[128][72] @0, B[128][72] @9216 halves; stride 18432 halves.
// total 2*36864 = 73728 B -> 2 CTA/SM (regs capped 128).
// ---------------------------------------------------------------------------
#define GEMM_SMEM 73728

template<bool OUT_FP16>
__global__ __launch_bounds__(256, 2)
void gemm_f16_kernel(const __half* __restrict__ A, const __half* __restrict__ BT,
                     const float* __restrict__ bias, void* __restrict__ outp, int ncols)
{
    extern __shared__ __half smh[];
    const uint32_t sb = smem_u32(smh);
    const int tid = threadIdx.x;
    const int w = tid >> 5, lane = tid & 31;
    const int g = lane >> 2, t = lane & 3;
    const int wm = w >> 1, wn = w & 1;
    const int n0 = blockIdx.x * 128;
    const int m0 = blockIdx.y * 128;

    const __half* Ab = A + (size_t)m0 * 256;
    const __half* Bb = BT + (size_t)n0 * 256;

    auto issue_load = [&](int kc, int stage) {
        uint32_t ab = sb + stage * (18432 * 2);
        uint32_t bb = ab + 9216 * 2;
        int k0 = kc * 64;
        #pragma unroll
        for (int it = 0; it < 4; ++it) {              // A: 1024 x 16B
            int idx = tid + it * 256;
            int r = idx >> 3, c = idx & 7;
            cp_async16(ab + (r * 72 + c * 8) * 2, Ab + (size_t)r * 256 + k0 + c * 8);
        }
        #pragma unroll
        for (int it = 0; it < 4; ++it) {              // B: 1024 x 16B
            int idx = tid + it * 256;
            int r = idx >> 3, c = idx & 7;
            cp_async16(bb + (r * 72 + c * 8) * 2, Bb + (size_t)r * 256 + k0 + c * 8);
        }
        asm volatile("cp.async.commit_group;" ::: "memory");
    };

    float d[2][8][4];
    #pragma unroll
    for (int i = 0; i < 2; ++i)
        #pragma unroll
        for (int j = 0; j < 8; ++j)
            #pragma unroll
            for (int q = 0; q < 4; ++q) d[i][j][q] = 0.f;

    // ldmatrix lane-address components
    const int arow  = lane & 15;
    const int akoff = (lane >> 4) * 8;
    const int bnrow = ((lane >> 4) << 3) + (lane & 7);
    const int bkoff = ((lane >> 3) & 1) * 8;

    auto compute = [&](int stage) {
        const uint32_t sAb = sb + stage * (18432 * 2);
        const uint32_t sBb = sAb + 9216 * 2;
        #pragma unroll
        for (int ks = 0; ks < 4; ++ks) {              // 4 x k16 = 64
            uint32_t a[2][4], bf[8][2];
            #pragma unroll
            for (int ii = 0; ii < 2; ++ii) {
                int row = wm * 32 + ii * 16 + arow;
                uint32_t addr = sAb + (row * 72 + ks * 16 + akoff) * 2;
                asm volatile(
                    "ldmatrix.sync.aligned.m8n8.x4.shared.b16 {%0,%1,%2,%3}, [%4];"
                    : "=r"(a[ii][0]), "=r"(a[ii][1]), "=r"(a[ii][2]), "=r"(a[ii][3])
                    : "r"(addr));
            }
            #pragma unroll
            for (int jp = 0; jp < 4; ++jp) {
                int n = wn * 64 + jp * 16 + bnrow;
                uint32_t addr = sBb + (n * 72 + ks * 16 + bkoff) * 2;
                asm volatile(
                    "ldmatrix.sync.aligned.m8n8.x4.shared.b16 {%0,%1,%2,%3}, [%4];"
                    : "=r"(bf[2 * jp][0]), "=r"(bf[2 * jp][1]),
                      "=r"(bf[2 * jp + 1][0]), "=r"(bf[2 * jp + 1][1])
                    : "r"(addr));
            }
            #pragma unroll
            for (int ii = 0; ii < 2; ++ii)
                #pragma unroll
                for (int j = 0; j < 8; ++j)
                    mma_f16(d[ii][j], a[ii], bf[j]);
        }
    };

    issue_load(0, 0);
    issue_load(1, 1);

    for (int i = 0; i < 4; ++i) {
        int buf = i & 1;
        if (i < 3) asm volatile("cp.async.wait_group 1;" ::: "memory");
        else       asm volatile("cp.async.wait_group 0;" ::: "memory");
        __syncthreads();
        compute(buf);
        __syncthreads();
        if (i + 2 < 4) issue_load(i + 2, buf);
    }

    #pragma unroll
    for (int ii = 0; ii < 2; ++ii) {
        int row = m0 + wm * 32 + ii * 16 + g;
        #pragma unroll
        for (int j = 0; j < 8; ++j) {
            int col = n0 + wn * 64 + j * 8 + 2 * t;
            float b0 = bias[col], b1 = bias[col + 1];
            if (OUT_FP16) {
                __half* oh = reinterpret_cast<__half*>(outp);
                uint32_t v0 = packh2(d[ii][j][0] + b0, d[ii][j][1] + b1);
                uint32_t v1 = packh2(d[ii][j][2] + b0, d[ii][j][3] + b1);
                *reinterpret_cast<uint32_t*>(oh + (size_t)row * ncols + col) = v0;
                *reinterpret_cast<uint32_t*>(oh + (size_t)(row + 8) * ncols + col) = v1;
            } else {
                float* of = reinterpret_cast<float*>(outp);
                *reinterpret_cast<float2*>(of + (size_t)row * ncols + col) =
                    make_float2(d[ii][j][0] + b0, d[ii][j][1] + b1);
                *reinterpret_cast<float2*>(of + (size_t)(row + 8) * ncols + col) =
                    make_float2(d[ii][j][2] + b0, d[ii][j][3] + b1);
            }
        }
    }
}

// ---------------------------------------------------------------------------
// attention (unchanged): 192 thr, register softmax, ldmatrix.trans V,
// head double-buffering, 4 CTA/SM.
// ---------------------------------------------------------------------------
#define ATTN_BUF 11520
#define ATTN_SMEM (2 * ATTN_BUF * 2)

__global__ __launch_bounds__(192, 4)
void attn_kernel()
{
    extern __shared__ __half smh[];
    const uint32_t sb = smem_u32(smh);
    const int tid = threadIdx.x;
    const int w = tid >> 5, l = tid & 31;
    const int g = l >> 2, t = l & 3;
    const int b = blockIdx.x;

    for (int i = tid; i < 480; i += 192) {
        int off = 7680 + (84 + i / 40) * 40 + (i % 40);
        smh[off] = __ushort_as_half(0);
        smh[ATTN_BUF + off] = __ushort_as_half(0);
    }

    const __half* qb = g_qkvh + (size_t)b * (NTOK * 768);

    auto issue_load = [&](int h, int buf) {
        uint32_t base = sb + buf * (ATTN_BUF * 2);
        const __half* src = qb + h * 32;
        for (int it = tid; it < 1008; it += 192) {
            int s = it / 336, r = it - s * 336;
            int n = r >> 2, c = r & 3;
            cp_async16(base + (s * 3840 + n * 40 + c * 8) * 2,
                       src + (size_t)n * 768 + s * 256 + c * 8);
        }
        asm volatile("cp.async.commit_group;" ::: "memory");
    };

    issue_load(0, 0);
    int buf = 0;

    for (int h = 0; h < HEADS; ++h) {
        if (h + 1 < HEADS) {
            issue_load(h + 1, buf ^ 1);
            asm volatile("cp.async.wait_group 1;" ::: "memory");
        } else {
            asm volatile("cp.async.wait_group 0;" ::: "memory");
        }
        __syncthreads();

        const uint32_t* sQw = reinterpret_cast<const uint32_t*>(smh + buf * ATTN_BUF);
        const uint32_t* sKw = reinterpret_cast<const uint32_t*>(smh + buf * ATTN_BUF + 3840);
        const uint32_t svb = sb + (buf * ATTN_BUF + 7680) * 2;

        float c4[12][4];
        #pragma unroll
        for (int ni = 0; ni < 12; ++ni)
            #pragma unroll
            for (int q = 0; q < 4; ++q) c4[ni][q] = 0.f;

        const int row = w * 16 + g;
        #pragma unroll
        for (int ks = 0; ks < 2; ++ks) {
            uint32_t a[4];
            a[0] = sQw[ row      * 20 + ks * 8 + t];
            a[1] = sQw[(row + 8) * 20 + ks * 8 + t];
            a[2] = sQw[ row      * 20 + ks * 8 + t + 4];
            a[3] = sQw[(row + 8) * 20 + ks * 8 + t + 4];
            #pragma unroll
            for (int ni = 0; ni < 12; ++ni) {
                uint32_t bf[2];
                bf[0] = sKw[(ni * 8 + g) * 20 + ks * 8 + t];
                bf[1] = sKw[(ni * 8 + g) * 20 + ks * 8 + t + 4];
                mma_f16(c4[ni], a, bf);
            }
        }

        const int r0 = row, r1 = row + 8;
        const bool v0r = r0 < NTOK, v1r = r1 < NTOK;
        const float* gb = g_bias + h * (NTOK * NTOK);
        #pragma unroll
        for (int ni = 0; ni < 12; ++ni) {
            int col = ni * 8 + 2 * t;
            if (col < NTOK) {
                if (v0r) {
                    float2 f = *reinterpret_cast<const float2*>(gb + r0 * NTOK + col);
                    c4[ni][0] += f.x; c4[ni][1] += f.y;
                }
                if (v1r) {
                    float2 f = *reinterpret_cast<const float2*>(gb + r1 * NTOK + col);
                    c4[ni][2] += f.x; c4[ni][3] += f.y;
                }
            }
        }
        float m0 = -1e30f, m1 = -1e30f;
        #pragma unroll
        for (int ni = 0; ni < 12; ++ni) {
            int col = ni * 8 + 2 * t;
            if (col < NTOK) {
                m0 = fmaxf(m0, fmaxf(c4[ni][0], c4[ni][1]));
                m1 = fmaxf(m1, fmaxf(c4[ni][2], c4[ni][3]));
            }
        }
        m0 = fmaxf(m0, __shfl_xor_sync(0xffffffffu, m0, 1));
        m0 = fmaxf(m0, __shfl_xor_sync(0xffffffffu, m0, 2));
        m1 = fmaxf(m1, __shfl_xor_sync(0xffffffffu, m1, 1));
        m1 = fmaxf(m1, __shfl_xor_sync(0xffffffffu, m1, 2));
        float s0 = 0.f, s1 = 0.f;
        #pragma unroll
        for (int ni = 0; ni < 12; ++ni) {
            int col = ni * 8 + 2 * t;
            if (col < NTOK) {
                c4[ni][0] = __expf(c4[ni][0] - m0);
                c4[ni][1] = __expf(c4[ni][1] - m0);
                c4[ni][2] = __expf(c4[ni][2] - m1);
                c4[ni][3] = __expf(c4[ni][3] - m1);
                s0 += c4[ni][0] + c4[ni][1];
                s1 += c4[ni][2] + c4[ni][3];
            } else {
                c4[ni][0] = c4[ni][1] = c4[ni][2] = c4[ni][3] = 0.f;
            }
        }
        s0 += __shfl_xor_sync(0xffffffffu, s0, 1);
        s0 += __shfl_xor_sync(0xffffffffu, s0, 2);
        s1 += __shfl_xor_sync(0xffffffffu, s1, 1);
        s1 += __shfl_xor_sync(0xffffffffu, s1, 2);
        const float i0 = 1.f / s0, i1 = 1.f / s1;
        #pragma unroll
        for (int ni = 0; ni < 12; ++ni) {
            c4[ni][0] *= i0; c4[ni][1] *= i0;
            c4[ni][2] *= i1; c4[ni][3] *= i1;
        }

        float o[4][4];
        #pragma unroll
        for (int nj = 0; nj < 4; ++nj)
            #pragma unroll
            for (int q = 0; q < 4; ++q) o[nj][q] = 0.f;

        #pragma unroll
        for (int ks = 0; ks < 6; ++ks) {
            uint32_t a[4];
            a[0] = packh2(c4[2 * ks][0],     c4[2 * ks][1]);
            a[1] = packh2(c4[2 * ks][2],     c4[2 * ks][3]);
            a[2] = packh2(c4[2 * ks + 1][0], c4[2 * ks + 1][1]);
            a[3] = packh2(c4[2 * ks + 1][2], c4[2 * ks + 1][3]);
            #pragma unroll
            for (int njp = 0; njp < 2; ++njp) {
                uint32_t r0m, r1m, r2m, r3m;
                uint32_t addr = svb +
                    (((ks * 16 + (l & 15)) * 40) + (njp * 2 + (l >> 4)) * 8) * 2;
                asm volatile(
                    "ldmatrix.sync.aligned.m8n8.x4.trans.shared.b16 {%0,%1,%2,%3}, [%4];"
                    : "=r"(r0m), "=r"(r1m), "=r"(r2m), "=r"(r3m) : "r"(addr));
                uint32_t bf0[2] = {r0m, r1m};
                uint32_t bf1[2] = {r2m, r3m};
                mma_f16(o[njp * 2],     a, bf0);
                mma_f16(o[njp * 2 + 1], a, bf1);
            }
        }

        __half* oa = g_attnh + (size_t)b * (NTOK * 256) + h * 32;
        #pragma unroll
        for (int nj = 0; nj < 4; ++nj) {
            int col = nj * 8 + 2 * t;
            if (v0r)
                *reinterpret_cast<uint32_t*>(oa + (size_t)r0 * 256 + col) =
                    packh2(o[nj][0], o[nj][1]);
            if (v1r)
                *reinterpret_cast<uint32_t*>(oa + (size_t)r1 * 256 + col) =
                    packh2(o[nj][2], o[nj][3]);
        }

        __syncthreads();
        buf ^= 1;
    }
}

// ---------------------------------------------------------------------------
extern "C" void kernel_launch(void* const* d_in, const int* in_sizes, int n_in,
                              void* d_out, int out_size)
{
    const float* x     = (const float*)d_in[0];
    const float* Wqkv  = (const float*)d_in[1];
    const float* bqkv  = (const float*)d_in[2];
    const float* Wp    = (const float*)d_in[3];
    const float* bp    = (const float*)d_in[4];
    const float* table = (const float*)d_in[5];
    const int*   ridx  = (const int*)d_in[6];
    float* out = (float*)d_out;

    cudaFuncSetAttribute(gemm_f16_kernel<true>,  cudaFuncAttributeMaxDynamicSharedMemorySize, GEMM_SMEM);
    cudaFuncSetAttribute(gemm_f16_kernel<false>, cudaFuncAttributeMaxDynamicSharedMemorySize, GEMM_SMEM);
    cudaFuncSetAttribute(attn_kernel, cudaFuncAttributeMaxDynamicSharedMemorySize, ATTN_SMEM);

    __half* xh;   cudaGetSymbolAddress((void**)&xh,   g_xh);
    __half* qkvh; cudaGetSymbolAddress((void**)&qkvh, g_qkvh);
    __half* ath;  cudaGetSymbolAddress((void**)&ath,  g_attnh);
    __half* wth;  cudaGetSymbolAddress((void**)&wth,  g_WTh);
    __half* wpth; cudaGetSymbolAddress((void**)&wpth, g_WpTh);
    float*  bq;   cudaGetSymbolAddress((void**)&bq,   g_bq);

    xprep_kernel<<<MROWS / 4, 256>>>(x);
    wprep_kernel<<<1024, 256>>>(Wqkv, Wp, bqkv);
    bias_kernel<<<28, 256>>>(table, ridx);
    gemm_f16_kernel<true><<<dim3(6, 1344), 256, GEMM_SMEM>>>(xh, wth, bq, qkvh, 768);
    attn_kernel<<<BATCH, 192, ATTN_SMEM>>>();
    gemm_f16_kernel<false><<<dim3(2, 1344), 256, GEMM_SMEM>>>(ath, wpth, bp, out, 256);
}